// round 11
// baseline (speedup 1.0000x reference)
#include <cuda_runtime.h>
#include <math.h>

#define B_      32
#define N_      325
#define L_      12
#define D_      128
#define H_      8
#define DK      16
#define BN      (B_*N_)        // 10400
#define ROWS    (BN*L_)        // 124800
#define MAXREL  11
#define LL      (L_*L_)        // 144
#define HLL     (H_*LL)        // 1152
#define PITCH   132
#define TT      2              // (b,n) tiles per fused block
#define MROWS   (TT*L_)        // 24 real rows (padded to 32 in smem)
#define NBF     (BN/TT)        // 5200
#define BROWS   32             // padded buffer rows
#define BUFSZ   (BROWS*PITCH)  // 4224 floats
#define MO      32             // out_kernel row-tile
#define NBO     (ROWS/MO)      // 3900

typedef unsigned int u32t;

// ---- static device scratch ----
__device__ __align__(16) u32t  g_Wfrag[4][D_*D_];   // tf32 weights in B-fragment order
__device__ __align__(16) float g_K2[LL*DK];
__device__ __align__(16) float g_V2[LL*DK];
__device__ __align__(16) float g_ctx[(size_t)ROWS*D_];
__device__ __align__(16) float g_psum[(size_t)BN*D_];    // [bn][c]
__device__ __align__(16) float g_psumsq[(size_t)BN*D_];  // [bn][c]
__device__ float g_scale[D_];
__device__ float g_shift[D_];

__device__ __forceinline__ u32t to_tf32(float x) {
    u32t t; asm("cvt.rna.tf32.f32 %0, %1;" : "=r"(t) : "f"(x)); return t;
}
__device__ __forceinline__ void mma_tf32(float c[4], const u32t a[4], u32t b0, u32t b1) {
    asm volatile("mma.sync.aligned.m16n8k8.row.col.f32.tf32.tf32.f32 "
                 "{%0,%1,%2,%3}, {%4,%5,%6,%7}, {%8,%9}, {%0,%1,%2,%3};"
                 : "+f"(c[0]), "+f"(c[1]), "+f"(c[2]), "+f"(c[3])
                 : "r"(a[0]), "r"(a[1]), "r"(a[2]), "r"(a[3]), "r"(b0), "r"(b1));
}

// ---------------------------------------------------------------------------
// Kernel 1: weight-norm -> tf32 B-fragment layout; rel-position tables
// ---------------------------------------------------------------------------
__global__ void prep_kernel(const float* __restrict__ wq_v, const float* __restrict__ wq_g,
                            const float* __restrict__ wk_v, const float* __restrict__ wk_g,
                            const float* __restrict__ wv_v, const float* __restrict__ wv_g,
                            const float* __restrict__ fc_v, const float* __restrict__ fc_g,
                            const float* __restrict__ rel_k, const float* __restrict__ rel_v) {
    int blk = blockIdx.x;
    if (blk < 4) {
        const float* v; const float* g;
        switch (blk) {
            case 0: v = wq_v; g = wq_g; break;
            case 1: v = wk_v; g = wk_g; break;
            case 2: v = wv_v; g = wv_g; break;
            default: v = fc_v; g = fc_g; break;
        }
        __shared__ float s_sc[D_];
        int r = threadIdx.x;
        float s = 0.f;
        for (int d = 0; d < D_; d++) { float x = v[r*D_ + d]; s += x*x; }
        s_sc[r] = g[r] * rsqrtf(s);
        __syncthreads();
        for (int idx = threadIdx.x; idx < D_*D_; idx += 128) {
            int rr   = idx & 1;
            int lane = (idx >> 1) & 31;
            int nn   = (idx >> 6) & 15;
            int kk   = idx >> 10;
            int k = kk*8 + (lane & 3) + 4*rr;
            int n = nn*8 + (lane >> 2);
            g_Wfrag[blk][idx] = to_tf32(v[n*D_ + k] * s_sc[n]);
        }
    } else {
        for (int t = threadIdx.x; t < LL; t += blockDim.x) {
            int q = t / L_, k = t % L_;
            int dist = max(-MAXREL, min(MAXREL, k - q));
            int row = dist + MAXREL;
            for (int d = 0; d < DK; d++) {
                g_K2[t*DK + d] = rel_k[row*DK + d];
                g_V2[t*DK + d] = rel_v[row*DK + d];
            }
        }
    }
}

// ---------------------------------------------------------------------------
// m16n32 warp-MMA over K=128 (uint2 B loads). Warp grid: mw in {0,1}, nw in 0..3.
// ---------------------------------------------------------------------------
__device__ __forceinline__ void mma_warp(const u32t* __restrict__ s_x,
                                         const u32t* __restrict__ Wf,
                                         int mw, int nw, int lane, float acc[4][4]) {
    const int g = lane >> 2, tig = lane & 3;
    #pragma unroll 4
    for (int kk = 0; kk < 16; kk++) {
        u32t a[4];
        const u32t* base = s_x + (mw*16 + g)*PITCH + kk*8 + tig;
        a[0] = base[0];
        a[1] = base[8*PITCH];
        a[2] = base[4];
        a[3] = base[8*PITCH + 4];
        const uint2* bp2 = (const uint2*)(Wf + (kk*16 + nw*4)*64) + lane;
        #pragma unroll
        for (int nn = 0; nn < 4; nn++) {
            uint2 b = bp2[nn*32];
            mma_tf32(acc[nn], a, b.x, b.y);
        }
    }
}
__device__ __forceinline__ void store_warp(float* __restrict__ dst,
                                           int mw, int nw, int lane, const float acc[4][4]) {
    const int g = lane >> 2, tig = lane & 3;
    const int row = mw*16 + g;
    const int colb = nw*32 + 2*tig;
    #pragma unroll
    for (int nn = 0; nn < 4; nn++) {
        *(float2*)(dst + row*PITCH + colb + nn*8)     = make_float2(acc[nn][0], acc[nn][1]);
        *(float2*)(dst + (row+8)*PITCH + colb + nn*8) = make_float2(acc[nn][2], acc[nn][3]);
    }
}

__device__ __forceinline__ void stage_tf32(const float* __restrict__ src, float* __restrict__ dst,
                                           int tid) {
    const float4* s4 = (const float4*)src;
    for (int i = tid; i < MROWS*32; i += 256) {
        float4 x = s4[i];
        int row = i >> 5, c4 = i & 31;
        uint4 t;
        t.x = to_tf32(x.x); t.y = to_tf32(x.y); t.z = to_tf32(x.z); t.w = to_tf32(x.w);
        ((uint4*)((u32t*)dst + row*PITCH))[c4] = t;
    }
}

// ---------------------------------------------------------------------------
// Kernel 2: FUSED projections + attention middle. 2 (b,n) tiles per block,
// 3 blocks/SM. All three GEMMs in ONE barrier-free region (acc[3][4][4]).
// ---------------------------------------------------------------------------
__global__ __launch_bounds__(256, 3) void fused_kernel(const float* __restrict__ inQ,
                                                       const float* __restrict__ inK,
                                                       const float* __restrict__ inV,
                                                       const float* __restrict__ w1,
                                                       const float* __restrict__ w2,
                                                       float* __restrict__ attn_out) {
    extern __shared__ __align__(16) float sm[];
    float* sA   = sm;                 // Xq tf32 -> Q fp32 -> s_at2
    float* sB   = sm + BUFSZ;         // Xk tf32 -> K fp32
    float* sC   = sm + 2*BUFSZ;       // Xv tf32 -> V fp32
    float* s_at = sm + 3*BUFSZ;       // 2304
    float* s_w1 = sm + 3*BUFSZ + TT*HLL;        // 64
    float* s_w2 = s_w1 + 64;                    // 64
    float* s_at2 = sA;

    const int tid  = threadIdx.x;
    const int lane = tid & 31, warp = tid >> 5;
    const int mw = warp >> 2, nw = warp & 3;
    const int bn0 = blockIdx.x * TT;
    const size_t gbase = (size_t)bn0 * (L_*D_);

    // ---- S0: stage all three inputs + mixing weights ----
    stage_tf32(inQ + gbase, sA, tid);
    stage_tf32(inK + gbase, sB, tid);
    stage_tf32(inV + gbase, sC, tid);
    if (tid < 64) { s_w1[tid] = w1[tid]; s_w2[tid] = w2[tid]; }
    __syncthreads();

    // ---- Q,K,V GEMMs: one barrier-free region, 192 weight LDGs pipelined ----
    {
        float acc[3][4][4];
        #pragma unroll
        for (int m = 0; m < 3; m++)
            #pragma unroll
            for (int nn = 0; nn < 4; nn++)
                #pragma unroll
                for (int q = 0; q < 4; q++) acc[m][nn][q] = 0.f;

        #pragma unroll
        for (int m = 0; m < 3; m++)
            mma_warp((const u32t*)(sm + m*BUFSZ), g_Wfrag[m], mw, nw, lane, acc[m]);

        __syncthreads();     // all reads of A/B/C complete
        #pragma unroll
        for (int m = 0; m < 3; m++)
            store_warp(sm + m*BUFSZ, mw, nw, lane, acc[m]);
    }
    __syncthreads();

    // ---- scores + w1 mix + leaky relu (accumulate w1 on the fly) ----
    for (int idx = tid; idx < TT*LL; idx += 256) {
        int t = idx / LL, rem = idx - t*LL;
        const int i = rem / L_, j = rem - i*L_;
        const float* qrow = sA + (t*L_ + i)*PITCH;
        const float* krow = sB + (t*L_ + j)*PITCH;
        const float4* k2 = (const float4*)(g_K2 + rem*DK);
        float4 r0 = k2[0], r1 = k2[1], r2 = k2[2], r3 = k2[3];
        float out[H_];
        #pragma unroll
        for (int g2 = 0; g2 < H_; g2++) out[g2] = 0.f;
        #pragma unroll
        for (int h = 0; h < H_; h++) {
            const float4* q4 = (const float4*)(qrow + h*DK);
            const float4* k4 = (const float4*)(krow + h*DK);
            float4 q0 = q4[0], q1 = q4[1], q2 = q4[2], q3 = q4[3];
            float4 k0 = k4[0], k1 = k4[1], k2v = k4[2], k3 = k4[3];
            float s = 0.f;
            s += q0.x*(k0.x+r0.x) + q0.y*(k0.y+r0.y) + q0.z*(k0.z+r0.z) + q0.w*(k0.w+r0.w);
            s += q1.x*(k1.x+r1.x) + q1.y*(k1.y+r1.y) + q1.z*(k1.z+r1.z) + q1.w*(k1.w+r1.w);
            s += q2.x*(k2v.x+r2.x) + q2.y*(k2v.y+r2.y) + q2.z*(k2v.z+r2.z) + q2.w*(k2v.w+r2.w);
            s += q3.x*(k3.x+r3.x) + q3.y*(k3.y+r3.y) + q3.z*(k3.z+r3.z) + q3.w*(k3.w+r3.w);
            s *= 0.25f;
            #pragma unroll
            for (int g2 = 0; g2 < H_; g2++) out[g2] = fmaf(s, s_w1[h*H_ + g2], out[g2]);
        }
        #pragma unroll
        for (int g2 = 0; g2 < H_; g2++) {
            float s = out[g2];
            s_at[t*HLL + g2*LL + rem] = (s > 0.f) ? s : 0.2f * s;
        }
    }
    __syncthreads();

    // ---- softmax over k: TT*96 rows of 12 ----
    for (int rowid = tid; rowid < TT*H_*L_; rowid += 256) {
        float* row = s_at + rowid * L_;
        float mx = row[0];
        #pragma unroll
        for (int j = 1; j < L_; j++) mx = fmaxf(mx, row[j]);
        float sum = 0.f;
        #pragma unroll
        for (int j = 0; j < L_; j++) { float e = __expf(row[j] - mx); row[j] = e; sum += e; }
        float inv = 1.f / sum;
        #pragma unroll
        for (int j = 0; j < L_; j++) row[j] *= inv;
    }
    __syncthreads();

    // ---- w2 mix -> s_at2 (A region; Q dead) + attn_ret write ----
    for (int idx = tid; idx < TT*LL; idx += 256) {
        int t = idx / LL, rem = idx - t*LL;
        int i = rem / L_, j = rem - i*L_;
        float a[H_];
        #pragma unroll
        for (int h = 0; h < H_; h++) a[h] = s_at[t*HLL + h*LL + rem];
        #pragma unroll
        for (int g2 = 0; g2 < H_; g2++) {
            float s = 0.f;
            #pragma unroll
            for (int h = 0; h < H_; h++) s = fmaf(a[h], s_w2[h*H_ + g2], s);
            s_at2[t*HLL + g2*LL + rem] = s;
            attn_out[(size_t)i * ((size_t)BN*96) + (size_t)(bn0+t)*96 + g2*L_ + j] = s;
        }
    }
    __syncthreads();

    // ---- context + BN partials (coalesced [bn][c] layout) ----
    {
        const int c = tid & 127;
        const int t = tid >> 7;           // TT = 2 tiles, 128 channels each
        const int h = c >> 4, d = c & 15;
        float vj[L_];
        #pragma unroll
        for (int j = 0; j < L_; j++) vj[j] = sC[(t*L_ + j)*PITCH + c];
        const float* at = s_at2 + t*HLL + h*LL;
        float* ctxp = g_ctx + (size_t)(bn0 + t) * (L_*D_);
        float sum = 0.f, sq = 0.f;
        #pragma unroll
        for (int i = 0; i < L_; i++) {
            float a2 = 0.f;
            #pragma unroll
            for (int j = 0; j < L_; j++)
                a2 = fmaf(at[i*L_ + j], vj[j] + __ldg(g_V2 + (i*L_ + j)*DK + d), a2);
            ctxp[i*D_ + c] = a2;
            sum += a2;
            sq = fmaf(a2, a2, sq);
        }
        g_psum  [(size_t)(bn0 + t)*D_ + c] = sum;
        g_psumsq[(size_t)(bn0 + t)*D_ + c] = sq;
    }
}

// ---------------------------------------------------------------------------
// Kernel 3: finalize BN stats. 32 blocks, block b -> channels [4b, 4b+4).
// ---------------------------------------------------------------------------
__global__ void stats_kernel(const float* __restrict__ gamma, const float* __restrict__ beta) {
    __shared__ float red[8][256];
    const int tid = threadIdx.x;
    const int cb  = blockIdx.x * 4;
    float4 s  = make_float4(0.f, 0.f, 0.f, 0.f);
    float4 sq = make_float4(0.f, 0.f, 0.f, 0.f);
    for (int bn = tid; bn < BN; bn += 256) {
        float4 p = *(const float4*)(g_psum   + (size_t)bn*D_ + cb);
        float4 q = *(const float4*)(g_psumsq + (size_t)bn*D_ + cb);
        s.x += p.x; s.y += p.y; s.z += p.z; s.w += p.w;
        sq.x += q.x; sq.y += q.y; sq.z += q.z; sq.w += q.w;
    }
    red[0][tid] = s.x;  red[1][tid] = s.y;  red[2][tid] = s.z;  red[3][tid] = s.w;
    red[4][tid] = sq.x; red[5][tid] = sq.y; red[6][tid] = sq.z; red[7][tid] = sq.w;
    __syncthreads();
    for (int st = 128; st > 0; st >>= 1) {
        if (tid < st) {
            #pragma unroll
            for (int j = 0; j < 8; j++) red[j][tid] += red[j][tid + st];
        }
        __syncthreads();
    }
    if (tid < 4) {
        const float invN = 1.f / (float)ROWS;
        int c = cb + tid;
        float mean = red[tid][0] * invN;
        float var  = red[tid + 4][0] * invN - mean*mean;
        float sc = rsqrtf(var + 1e-5f) * gamma[c];
        g_scale[c] = sc;
        g_shift[c] = beta[c] - mean * sc;
    }
}

// ---------------------------------------------------------------------------
// Kernel 4: BN-apply + fc GEMM + ReLU + residual. M=32 tiles, grid=NBO.
// ---------------------------------------------------------------------------
__global__ __launch_bounds__(256, 4) void out_kernel(const float* __restrict__ inV,
                                                     float* __restrict__ out) {
    __shared__ __align__(16) u32t s_x[MO*PITCH];
    __shared__ float s_scale[D_], s_shift[D_];
    const int tid = threadIdx.x;
    const size_t base = (size_t)blockIdx.x * MO * D_;

    if (tid < D_) { s_scale[tid] = g_scale[tid]; s_shift[tid] = g_shift[tid]; }
    __syncthreads();

    const float4* ctx4 = (const float4*)(g_ctx + base);
    const float4* sc4 = (const float4*)s_scale;
    const float4* sh4 = (const float4*)s_shift;
    for (int i = tid; i < MO*32; i += 256) {
        float4 x = ctx4[i];
        float4 sc = sc4[i & 31], sh = sh4[i & 31];
        int row = i >> 5, c4 = i & 31;
        uint4 t;
        t.x = to_tf32(x.x*sc.x + sh.x);
        t.y = to_tf32(x.y*sc.y + sh.y);
        t.z = to_tf32(x.z*sc.z + sh.z);
        t.w = to_tf32(x.w*sc.w + sh.w);
        ((uint4*)(s_x + row*PITCH))[c4] = t;
    }
    __syncthreads();

    const int lane = tid & 31, warp = tid >> 5;
    const int mw = warp & 1, nw = warp >> 1;
    const int g = lane >> 2, tig = lane & 3;

    float acc[4][4];
    #pragma unroll
    for (int nn = 0; nn < 4; nn++)
        #pragma unroll
        for (int q = 0; q < 4; q++) acc[nn][q] = 0.f;

    #pragma unroll 4
    for (int kk = 0; kk < 16; kk++) {
        u32t a[4];
        const u32t* abase = s_x + (mw*16 + g)*PITCH + kk*8 + tig;
        a[0] = abase[0];
        a[1] = abase[8*PITCH];
        a[2] = abase[4];
        a[3] = abase[8*PITCH + 4];
        const uint2* bp2 = (const uint2*)(g_Wfrag[3] + (kk*16 + nw*4)*64) + lane;
        #pragma unroll
        for (int nn = 0; nn < 4; nn++) {
            uint2 b = bp2[nn*32];
            mma_tf32(acc[nn], a, b.x, b.y);
        }
    }

    const float* vin = inV + base;
    float* dst = out + base;
    const int row = mw*16 + g;
    const int colb = nw*32 + 2*tig;
    #pragma unroll
    for (int nn = 0; nn < 4; nn++) {
        int col = colb + nn*8;
        float2 v0 = *(const float2*)(vin + (size_t)row*D_ + col);
        float2 v1 = *(const float2*)(vin + (size_t)(row+8)*D_ + col);
        float2 o0, o1;
        o0.x = fmaxf(acc[nn][0], 0.f) + v0.x;
        o0.y = fmaxf(acc[nn][1], 0.f) + v0.y;
        o1.x = fmaxf(acc[nn][2], 0.f) + v1.x;
        o1.y = fmaxf(acc[nn][3], 0.f) + v1.y;
        *(float2*)(dst + (size_t)row*D_ + col)     = o0;
        *(float2*)(dst + (size_t)(row+8)*D_ + col) = o1;
    }
}

// ---------------------------------------------------------------------------
extern "C" void kernel_launch(void* const* d_in, const int* in_sizes, int n_in,
                              void* d_out, int out_size) {
    const float* inQ   = (const float*)d_in[0];
    const float* inK   = (const float*)d_in[1];
    const float* inV   = (const float*)d_in[2];
    const float* wq_v  = (const float*)d_in[3];
    const float* wq_g  = (const float*)d_in[4];
    const float* wk_v  = (const float*)d_in[5];
    const float* wk_g  = (const float*)d_in[6];
    const float* wv_v  = (const float*)d_in[7];
    const float* wv_g  = (const float*)d_in[8];
    const float* fc_v  = (const float*)d_in[9];
    const float* fc_g  = (const float*)d_in[10];
    const float* rel_k = (const float*)d_in[11];
    const float* rel_v = (const float*)d_in[12];
    const float* w1    = (const float*)d_in[13];
    const float* w2    = (const float*)d_in[14];
    const float* gamma = (const float*)d_in[15];
    const float* beta  = (const float*)d_in[16];

    float* out      = (float*)d_out;
    float* attn_out = out + (size_t)ROWS * D_;

    const int fused_smem = (3*BUFSZ + TT*HLL + 128) * (int)sizeof(float);   // 60,416 B
    cudaFuncSetAttribute(fused_kernel, cudaFuncAttributeMaxDynamicSharedMemorySize, fused_smem);

    prep_kernel<<<5, 128>>>(wq_v, wq_g, wk_v, wk_g, wv_v, wv_g, fc_v, fc_g, rel_k, rel_v);
    fused_kernel<<<NBF, 256, fused_smem>>>(inQ, inK, inV, w1, w2, attn_out);
    stats_kernel<<<32, 256>>>(gamma, beta);
    out_kernel<<<NBO, 256>>>(inV, out);
}

// round 12
// speedup vs baseline: 1.0279x; 1.0279x over previous
#include <cuda_runtime.h>
#include <math.h>

#define B_      32
#define N_      325
#define L_      12
#define D_      128
#define H_      8
#define DK      16
#define BN      (B_*N_)        // 10400
#define ROWS    (BN*L_)        // 124800
#define MAXREL  11
#define LL      (L_*L_)        // 144
#define HLL     (H_*LL)        // 1152
#define PITCH   132
#define TT      2              // (b,n) tiles per fused block
#define MROWS   (TT*L_)        // 24 real rows (padded to 32 in smem)
#define NBF     (BN/TT)        // 5200
#define BROWS   32             // padded buffer rows
#define BUFSZ   (BROWS*PITCH)  // 4224 floats
#define MO      32             // out_kernel row-tile
#define NBO     (ROWS/MO)      // 3900

typedef unsigned int u32t;

// ---- static device scratch ----
__device__ __align__(16) u32t  g_Wfrag[4][D_*D_];   // tf32 weights in B-fragment order
__device__ __align__(16) float g_K2[LL*DK];
__device__ __align__(16) float g_V2[LL*DK];
__device__ __align__(16) float g_ctx[(size_t)ROWS*D_];
__device__ __align__(16) float g_psum[(size_t)BN*D_];    // [bn][c]
__device__ __align__(16) float g_psumsq[(size_t)BN*D_];  // [bn][c]
__device__ float g_scale[D_];
__device__ float g_shift[D_];

__device__ __forceinline__ u32t to_tf32(float x) {
    u32t t; asm("cvt.rna.tf32.f32 %0, %1;" : "=r"(t) : "f"(x)); return t;
}
__device__ __forceinline__ void mma_tf32(float c[4], const u32t a[4], u32t b0, u32t b1) {
    asm volatile("mma.sync.aligned.m16n8k8.row.col.f32.tf32.tf32.f32 "
                 "{%0,%1,%2,%3}, {%4,%5,%6,%7}, {%8,%9}, {%0,%1,%2,%3};"
                 : "+f"(c[0]), "+f"(c[1]), "+f"(c[2]), "+f"(c[3])
                 : "r"(a[0]), "r"(a[1]), "r"(a[2]), "r"(a[3]), "r"(b0), "r"(b1));
}

// ---------------------------------------------------------------------------
// Kernel 1: weight-norm -> tf32 B-fragment layout; rel-position tables
// ---------------------------------------------------------------------------
__global__ void prep_kernel(const float* __restrict__ wq_v, const float* __restrict__ wq_g,
                            const float* __restrict__ wk_v, const float* __restrict__ wk_g,
                            const float* __restrict__ wv_v, const float* __restrict__ wv_g,
                            const float* __restrict__ fc_v, const float* __restrict__ fc_g,
                            const float* __restrict__ rel_k, const float* __restrict__ rel_v) {
    int blk = blockIdx.x;
    if (blk < 4) {
        const float* v; const float* g;
        switch (blk) {
            case 0: v = wq_v; g = wq_g; break;
            case 1: v = wk_v; g = wk_g; break;
            case 2: v = wv_v; g = wv_g; break;
            default: v = fc_v; g = fc_g; break;
        }
        __shared__ float s_sc[D_];
        int r = threadIdx.x;
        float s = 0.f;
        for (int d = 0; d < D_; d++) { float x = v[r*D_ + d]; s += x*x; }
        s_sc[r] = g[r] * rsqrtf(s);
        __syncthreads();
        for (int idx = threadIdx.x; idx < D_*D_; idx += 128) {
            int rr   = idx & 1;
            int lane = (idx >> 1) & 31;
            int nn   = (idx >> 6) & 15;
            int kk   = idx >> 10;
            int k = kk*8 + (lane & 3) + 4*rr;
            int n = nn*8 + (lane >> 2);
            g_Wfrag[blk][idx] = to_tf32(v[n*D_ + k] * s_sc[n]);
        }
    } else {
        for (int t = threadIdx.x; t < LL; t += blockDim.x) {
            int q = t / L_, k = t % L_;
            int dist = max(-MAXREL, min(MAXREL, k - q));
            int row = dist + MAXREL;
            for (int d = 0; d < DK; d++) {
                g_K2[t*DK + d] = rel_k[row*DK + d];
                g_V2[t*DK + d] = rel_v[row*DK + d];
            }
        }
    }
}

// ---------------------------------------------------------------------------
// m32n16 warp-MMA over K=128: warp nw (0..7) owns columns nw*16..+16, all 32
// rows. Each B-fragment load is shared by 2 A-fragments (no duplication).
// ---------------------------------------------------------------------------
__device__ __forceinline__ void mma_warp32(const u32t* __restrict__ s_x,
                                           const u32t* __restrict__ Wf,
                                           int nw, int lane, float acc[2][2][4]) {
    const int g = lane >> 2, tig = lane & 3;
    #pragma unroll 4
    for (int kk = 0; kk < 16; kk++) {
        u32t a[2][4];
        #pragma unroll
        for (int mt = 0; mt < 2; mt++) {
            const u32t* base = s_x + (mt*16 + g)*PITCH + kk*8 + tig;
            a[mt][0] = base[0];
            a[mt][1] = base[8*PITCH];
            a[mt][2] = base[4];
            a[mt][3] = base[8*PITCH + 4];
        }
        const uint2* bp2 = (const uint2*)(Wf + (kk*16 + nw*2)*64) + lane;
        #pragma unroll
        for (int nn = 0; nn < 2; nn++) {
            uint2 b = bp2[nn*32];
            mma_tf32(acc[0][nn], a[0], b.x, b.y);
            mma_tf32(acc[1][nn], a[1], b.x, b.y);
        }
    }
}
__device__ __forceinline__ void store_warp32(float* __restrict__ dst,
                                             int nw, int lane, const float acc[2][2][4]) {
    const int g = lane >> 2, tig = lane & 3;
    const int colb = nw*16 + 2*tig;
    #pragma unroll
    for (int mt = 0; mt < 2; mt++) {
        const int row = mt*16 + g;
        #pragma unroll
        for (int nn = 0; nn < 2; nn++) {
            *(float2*)(dst + row*PITCH + colb + nn*8)     = make_float2(acc[mt][nn][0], acc[mt][nn][1]);
            *(float2*)(dst + (row+8)*PITCH + colb + nn*8) = make_float2(acc[mt][nn][2], acc[mt][nn][3]);
        }
    }
}

__device__ __forceinline__ void stage_tf32(const float* __restrict__ src, float* __restrict__ dst,
                                           int tid) {
    const float4* s4 = (const float4*)src;
    for (int i = tid; i < MROWS*32; i += 256) {
        float4 x = s4[i];
        int row = i >> 5, c4 = i & 31;
        uint4 t;
        t.x = to_tf32(x.x); t.y = to_tf32(x.y); t.z = to_tf32(x.z); t.w = to_tf32(x.w);
        ((uint4*)((u32t*)dst + row*PITCH))[c4] = t;
    }
}

// ---------------------------------------------------------------------------
// Kernel 2: FUSED projections + attention middle. 2 (b,n) tiles per block,
// 3 blocks/SM. Three GEMMs in one region; m32n16 warp tiles (no dup weights).
// ---------------------------------------------------------------------------
__global__ __launch_bounds__(256, 3) void fused_kernel(const float* __restrict__ inQ,
                                                       const float* __restrict__ inK,
                                                       const float* __restrict__ inV,
                                                       const float* __restrict__ w1,
                                                       const float* __restrict__ w2,
                                                       float* __restrict__ attn_out) {
    extern __shared__ __align__(16) float sm[];
    float* sA   = sm;                 // Xq tf32 -> Q fp32 -> s_at2
    float* sB   = sm + BUFSZ;         // Xk tf32 -> K fp32
    float* sC   = sm + 2*BUFSZ;       // Xv tf32 -> V fp32
    float* s_at = sm + 3*BUFSZ;       // 2304
    float* s_w1 = sm + 3*BUFSZ + TT*HLL;        // 64
    float* s_w2 = s_w1 + 64;                    // 64
    float* s_at2 = sA;

    const int tid  = threadIdx.x;
    const int lane = tid & 31, warp = tid >> 5;
    const int bn0 = blockIdx.x * TT;
    const size_t gbase = (size_t)bn0 * (L_*D_);

    // ---- S0: stage all three inputs + mixing weights ----
    stage_tf32(inQ + gbase, sA, tid);
    stage_tf32(inK + gbase, sB, tid);
    stage_tf32(inV + gbase, sC, tid);
    if (tid < 64) { s_w1[tid] = w1[tid]; s_w2[tid] = w2[tid]; }
    __syncthreads();

    // ---- Q,K,V GEMMs: one barrier-free region ----
    {
        float acc[3][2][2][4];
        #pragma unroll
        for (int m = 0; m < 3; m++)
            #pragma unroll
            for (int mt = 0; mt < 2; mt++)
                #pragma unroll
                for (int nn = 0; nn < 2; nn++)
                    #pragma unroll
                    for (int q = 0; q < 4; q++) acc[m][mt][nn][q] = 0.f;

        #pragma unroll
        for (int m = 0; m < 3; m++)
            mma_warp32((const u32t*)(sm + m*BUFSZ), g_Wfrag[m], warp, lane, acc[m]);

        __syncthreads();     // all reads of A/B/C complete
        #pragma unroll
        for (int m = 0; m < 3; m++)
            store_warp32(sm + m*BUFSZ, warp, lane, acc[m]);
    }
    __syncthreads();

    // ---- scores + w1 mix + leaky relu (accumulate w1 on the fly) ----
    for (int idx = tid; idx < TT*LL; idx += 256) {
        int t = idx / LL, rem = idx - t*LL;
        const int i = rem / L_, j = rem - i*L_;
        const float* qrow = sA + (t*L_ + i)*PITCH;
        const float* krow = sB + (t*L_ + j)*PITCH;
        const float4* k2 = (const float4*)(g_K2 + rem*DK);
        float4 r0 = k2[0], r1 = k2[1], r2 = k2[2], r3 = k2[3];
        float out[H_];
        #pragma unroll
        for (int g2 = 0; g2 < H_; g2++) out[g2] = 0.f;
        #pragma unroll
        for (int h = 0; h < H_; h++) {
            const float4* q4 = (const float4*)(qrow + h*DK);
            const float4* k4 = (const float4*)(krow + h*DK);
            float4 q0 = q4[0], q1 = q4[1], q2 = q4[2], q3 = q4[3];
            float4 k0 = k4[0], k1 = k4[1], k2v = k4[2], k3 = k4[3];
            float s = 0.f;
            s += q0.x*(k0.x+r0.x) + q0.y*(k0.y+r0.y) + q0.z*(k0.z+r0.z) + q0.w*(k0.w+r0.w);
            s += q1.x*(k1.x+r1.x) + q1.y*(k1.y+r1.y) + q1.z*(k1.z+r1.z) + q1.w*(k1.w+r1.w);
            s += q2.x*(k2v.x+r2.x) + q2.y*(k2v.y+r2.y) + q2.z*(k2v.z+r2.z) + q2.w*(k2v.w+r2.w);
            s += q3.x*(k3.x+r3.x) + q3.y*(k3.y+r3.y) + q3.z*(k3.z+r3.z) + q3.w*(k3.w+r3.w);
            s *= 0.25f;
            #pragma unroll
            for (int g2 = 0; g2 < H_; g2++) out[g2] = fmaf(s, s_w1[h*H_ + g2], out[g2]);
        }
        #pragma unroll
        for (int g2 = 0; g2 < H_; g2++) {
            float s = out[g2];
            s_at[t*HLL + g2*LL + rem] = (s > 0.f) ? s : 0.2f * s;
        }
    }
    __syncthreads();

    // ---- softmax over k: TT*96 rows of 12 ----
    for (int rowid = tid; rowid < TT*H_*L_; rowid += 256) {
        float* row = s_at + rowid * L_;
        float mx = row[0];
        #pragma unroll
        for (int j = 1; j < L_; j++) mx = fmaxf(mx, row[j]);
        float sum = 0.f;
        #pragma unroll
        for (int j = 0; j < L_; j++) { float e = __expf(row[j] - mx); row[j] = e; sum += e; }
        float inv = 1.f / sum;
        #pragma unroll
        for (int j = 0; j < L_; j++) row[j] *= inv;
    }
    __syncthreads();

    // ---- w2 mix -> s_at2 (A region; Q dead) + attn_ret write ----
    for (int idx = tid; idx < TT*LL; idx += 256) {
        int t = idx / LL, rem = idx - t*LL;
        int i = rem / L_, j = rem - i*L_;
        float a[H_];
        #pragma unroll
        for (int h = 0; h < H_; h++) a[h] = s_at[t*HLL + h*LL + rem];
        #pragma unroll
        for (int g2 = 0; g2 < H_; g2++) {
            float s = 0.f;
            #pragma unroll
            for (int h = 0; h < H_; h++) s = fmaf(a[h], s_w2[h*H_ + g2], s);
            s_at2[t*HLL + g2*LL + rem] = s;
            attn_out[(size_t)i * ((size_t)BN*96) + (size_t)(bn0+t)*96 + g2*L_ + j] = s;
        }
    }
    __syncthreads();

    // ---- context + BN partials (coalesced [bn][c] layout) ----
    {
        const int c = tid & 127;
        const int t = tid >> 7;           // TT = 2 tiles, 128 channels each
        const int h = c >> 4, d = c & 15;
        float vj[L_];
        #pragma unroll
        for (int j = 0; j < L_; j++) vj[j] = sC[(t*L_ + j)*PITCH + c];
        const float* at = s_at2 + t*HLL + h*LL;
        float* ctxp = g_ctx + (size_t)(bn0 + t) * (L_*D_);
        float sum = 0.f, sq = 0.f;
        #pragma unroll
        for (int i = 0; i < L_; i++) {
            float a2 = 0.f;
            #pragma unroll
            for (int j = 0; j < L_; j++)
                a2 = fmaf(at[i*L_ + j], vj[j] + __ldg(g_V2 + (i*L_ + j)*DK + d), a2);
            ctxp[i*D_ + c] = a2;
            sum += a2;
            sq = fmaf(a2, a2, sq);
        }
        g_psum  [(size_t)(bn0 + t)*D_ + c] = sum;
        g_psumsq[(size_t)(bn0 + t)*D_ + c] = sq;
    }
}

// ---------------------------------------------------------------------------
// Kernel 3: finalize BN stats. 32 blocks, block b -> channels [4b, 4b+4).
// ---------------------------------------------------------------------------
__global__ void stats_kernel(const float* __restrict__ gamma, const float* __restrict__ beta) {
    __shared__ float red[8][256];
    const int tid = threadIdx.x;
    const int cb  = blockIdx.x * 4;
    float4 s  = make_float4(0.f, 0.f, 0.f, 0.f);
    float4 sq = make_float4(0.f, 0.f, 0.f, 0.f);
    for (int bn = tid; bn < BN; bn += 256) {
        float4 p = *(const float4*)(g_psum   + (size_t)bn*D_ + cb);
        float4 q = *(const float4*)(g_psumsq + (size_t)bn*D_ + cb);
        s.x += p.x; s.y += p.y; s.z += p.z; s.w += p.w;
        sq.x += q.x; sq.y += q.y; sq.z += q.z; sq.w += q.w;
    }
    red[0][tid] = s.x;  red[1][tid] = s.y;  red[2][tid] = s.z;  red[3][tid] = s.w;
    red[4][tid] = sq.x; red[5][tid] = sq.y; red[6][tid] = sq.z; red[7][tid] = sq.w;
    __syncthreads();
    for (int st = 128; st > 0; st >>= 1) {
        if (tid < st) {
            #pragma unroll
            for (int j = 0; j < 8; j++) red[j][tid] += red[j][tid + st];
        }
        __syncthreads();
    }
    if (tid < 4) {
        const float invN = 1.f / (float)ROWS;
        int c = cb + tid;
        float mean = red[tid][0] * invN;
        float var  = red[tid + 4][0] * invN - mean*mean;
        float sc = rsqrtf(var + 1e-5f) * gamma[c];
        g_scale[c] = sc;
        g_shift[c] = beta[c] - mean * sc;
    }
}

// ---------------------------------------------------------------------------
// Kernel 4: BN-apply + fc GEMM + ReLU + residual. M=32 tiles, m32n16 warps.
// ---------------------------------------------------------------------------
__global__ __launch_bounds__(256, 4) void out_kernel(const float* __restrict__ inV,
                                                     float* __restrict__ out) {
    __shared__ __align__(16) u32t s_x[MO*PITCH];
    __shared__ float s_scale[D_], s_shift[D_];
    const int tid = threadIdx.x;
    const size_t base = (size_t)blockIdx.x * MO * D_;

    if (tid < D_) { s_scale[tid] = g_scale[tid]; s_shift[tid] = g_shift[tid]; }
    __syncthreads();

    const float4* ctx4 = (const float4*)(g_ctx + base);
    const float4* sc4 = (const float4*)s_scale;
    const float4* sh4 = (const float4*)s_shift;
    for (int i = tid; i < MO*32; i += 256) {
        float4 x = ctx4[i];
        float4 sc = sc4[i & 31], sh = sh4[i & 31];
        int row = i >> 5, c4 = i & 31;
        uint4 t;
        t.x = to_tf32(x.x*sc.x + sh.x);
        t.y = to_tf32(x.y*sc.y + sh.y);
        t.z = to_tf32(x.z*sc.z + sh.z);
        t.w = to_tf32(x.w*sc.w + sh.w);
        ((uint4*)(s_x + row*PITCH))[c4] = t;
    }
    __syncthreads();

    const int lane = tid & 31, warp = tid >> 5;
    const int g = lane >> 2, tig = lane & 3;

    float acc[2][2][4];
    #pragma unroll
    for (int mt = 0; mt < 2; mt++)
        #pragma unroll
        for (int nn = 0; nn < 2; nn++)
            #pragma unroll
            for (int q = 0; q < 4; q++) acc[mt][nn][q] = 0.f;

    mma_warp32(s_x, g_Wfrag[3], warp, lane, acc);

    const float* vin = inV + base;
    float* dst = out + base;
    const int colb = warp*16 + 2*tig;
    #pragma unroll
    for (int mt = 0; mt < 2; mt++) {
        const int row = mt*16 + g;
        #pragma unroll
        for (int nn = 0; nn < 2; nn++) {
            int col = colb + nn*8;
            float2 v0 = *(const float2*)(vin + (size_t)row*D_ + col);
            float2 v1 = *(const float2*)(vin + (size_t)(row+8)*D_ + col);
            float2 o0, o1;
            o0.x = fmaxf(acc[mt][nn][0], 0.f) + v0.x;
            o0.y = fmaxf(acc[mt][nn][1], 0.f) + v0.y;
            o1.x = fmaxf(acc[mt][nn][2], 0.f) + v1.x;
            o1.y = fmaxf(acc[mt][nn][3], 0.f) + v1.y;
            *(float2*)(dst + (size_t)row*D_ + col)     = o0;
            *(float2*)(dst + (size_t)(row+8)*D_ + col) = o1;
        }
    }
}

// ---------------------------------------------------------------------------
extern "C" void kernel_launch(void* const* d_in, const int* in_sizes, int n_in,
                              void* d_out, int out_size) {
    const float* inQ   = (const float*)d_in[0];
    const float* inK   = (const float*)d_in[1];
    const float* inV   = (const float*)d_in[2];
    const float* wq_v  = (const float*)d_in[3];
    const float* wq_g  = (const float*)d_in[4];
    const float* wk_v  = (const float*)d_in[5];
    const float* wk_g  = (const float*)d_in[6];
    const float* wv_v  = (const float*)d_in[7];
    const float* wv_g  = (const float*)d_in[8];
    const float* fc_v  = (const float*)d_in[9];
    const float* fc_g  = (const float*)d_in[10];
    const float* rel_k = (const float*)d_in[11];
    const float* rel_v = (const float*)d_in[12];
    const float* w1    = (const float*)d_in[13];
    const float* w2    = (const float*)d_in[14];
    const float* gamma = (const float*)d_in[15];
    const float* beta  = (const float*)d_in[16];

    float* out      = (float*)d_out;
    float* attn_out = out + (size_t)ROWS * D_;

    const int fused_smem = (3*BUFSZ + TT*HLL + 128) * (int)sizeof(float);   // 60,416 B
    cudaFuncSetAttribute(fused_kernel, cudaFuncAttributeMaxDynamicSharedMemorySize, fused_smem);

    prep_kernel<<<5, 128>>>(wq_v, wq_g, wk_v, wk_g, wv_v, wv_g, fc_v, fc_g, rel_k, rel_v);
    fused_kernel<<<NBF, 256, fused_smem>>>(inQ, inK, inV, w1, w2, attn_out);
    stats_kernel<<<32, 256>>>(gamma, beta);
    out_kernel<<<NBO, 256>>>(inV, out);
}

// round 13
// speedup vs baseline: 1.0296x; 1.0016x over previous
#include <cuda_runtime.h>
#include <math.h>

#define B_      32
#define N_      325
#define L_      12
#define D_      128
#define H_      8
#define DK      16
#define BN      (B_*N_)        // 10400
#define ROWS    (BN*L_)        // 124800
#define MAXREL  11
#define LL      (L_*L_)        // 144
#define HLL     (H_*LL)        // 1152
#define PITCH   132
#define TT      2              // (b,n) tiles per fused block
#define MROWS   (TT*L_)        // 24 real rows (padded to 32 in smem)
#define NBF     (BN/TT)        // 5200
#define BROWS   32             // padded buffer rows
#define BUFSZ   (BROWS*PITCH)  // 4224 floats
#define MO      32             // out_kernel row-tile
#define NBO     (ROWS/MO)      // 3900

typedef unsigned int u32t;

// ---- static device scratch ----
// Quad-packed tf32 weights: uint4[(kk*8+nw)*32 + lane] =
//   { nn0:b0, nn0:b1, nn1:b0, nn1:b1 } for warp nw's two n8-fragments at kk.
__device__ __align__(16) u32t  g_Wfrag[4][D_*D_];
__device__ __align__(16) float g_K2[LL*DK];
__device__ __align__(16) float g_V2[LL*DK];
__device__ __align__(16) float g_ctx[(size_t)ROWS*D_];
__device__ __align__(16) float g_psum[(size_t)BN*D_];    // [bn][c]
__device__ __align__(16) float g_psumsq[(size_t)BN*D_];  // [bn][c]
__device__ float g_scale[D_];
__device__ float g_shift[D_];

__device__ __forceinline__ u32t to_tf32(float x) {
    u32t t; asm("cvt.rna.tf32.f32 %0, %1;" : "=r"(t) : "f"(x)); return t;
}
__device__ __forceinline__ void mma_tf32(float c[4], const u32t a[4], u32t b0, u32t b1) {
    asm volatile("mma.sync.aligned.m16n8k8.row.col.f32.tf32.tf32.f32 "
                 "{%0,%1,%2,%3}, {%4,%5,%6,%7}, {%8,%9}, {%0,%1,%2,%3};"
                 : "+f"(c[0]), "+f"(c[1]), "+f"(c[2]), "+f"(c[3])
                 : "r"(a[0]), "r"(a[1]), "r"(a[2]), "r"(a[3]), "r"(b0), "r"(b1));
}

// ---------------------------------------------------------------------------
// Kernel 1: weight-norm -> quad-packed tf32 fragment layout; rel tables
// ---------------------------------------------------------------------------
__global__ void prep_kernel(const float* __restrict__ wq_v, const float* __restrict__ wq_g,
                            const float* __restrict__ wk_v, const float* __restrict__ wk_g,
                            const float* __restrict__ wv_v, const float* __restrict__ wv_g,
                            const float* __restrict__ fc_v, const float* __restrict__ fc_g,
                            const float* __restrict__ rel_k, const float* __restrict__ rel_v) {
    int blk = blockIdx.x;
    if (blk < 4) {
        const float* v; const float* g;
        switch (blk) {
            case 0: v = wq_v; g = wq_g; break;
            case 1: v = wk_v; g = wk_g; break;
            case 2: v = wv_v; g = wv_g; break;
            default: v = fc_v; g = fc_g; break;
        }
        __shared__ float s_sc[D_];
        int r = threadIdx.x;
        float s = 0.f;
        for (int d = 0; d < D_; d++) { float x = v[r*D_ + d]; s += x*x; }
        s_sc[r] = g[r] * rsqrtf(s);
        __syncthreads();
        for (int idx = threadIdx.x; idx < D_*D_; idx += 128) {
            int r2   = idx & 3;           // word within uint4
            int lane = (idx >> 2) & 31;
            int nw   = (idx >> 7) & 7;
            int kk   = idx >> 10;
            int nn = nw*2 + (r2 >> 1);
            int rr = r2 & 1;
            int k = kk*8 + (lane & 3) + 4*rr;
            int n = nn*8 + (lane >> 2);
            g_Wfrag[blk][idx] = to_tf32(v[n*D_ + k] * s_sc[n]);
        }
    } else {
        for (int t = threadIdx.x; t < LL; t += blockDim.x) {
            int q = t / L_, k = t % L_;
            int dist = max(-MAXREL, min(MAXREL, k - q));
            int row = dist + MAXREL;
            for (int d = 0; d < DK; d++) {
                g_K2[t*DK + d] = rel_k[row*DK + d];
                g_V2[t*DK + d] = rel_v[row*DK + d];
            }
        }
    }
}

// ---------------------------------------------------------------------------
// m32n16 warp-MMA over K=128: warp nw owns cols nw*16..+16, all 32 rows.
// ONE LDG.128 per kk loads both n-fragments.
// ---------------------------------------------------------------------------
__device__ __forceinline__ void mma_warp32(const u32t* __restrict__ s_x,
                                           const u32t* __restrict__ Wf,
                                           int nw, int lane, float acc[2][2][4]) {
    const int g = lane >> 2, tig = lane & 3;
    const uint4* __restrict__ Wq = (const uint4*)Wf;
    #pragma unroll 4
    for (int kk = 0; kk < 16; kk++) {
        u32t a[2][4];
        #pragma unroll
        for (int mt = 0; mt < 2; mt++) {
            const u32t* base = s_x + (mt*16 + g)*PITCH + kk*8 + tig;
            a[mt][0] = base[0];
            a[mt][1] = base[8*PITCH];
            a[mt][2] = base[4];
            a[mt][3] = base[8*PITCH + 4];
        }
        uint4 b = Wq[(kk*8 + nw)*32 + lane];
        mma_tf32(acc[0][0], a[0], b.x, b.y);
        mma_tf32(acc[1][0], a[1], b.x, b.y);
        mma_tf32(acc[0][1], a[0], b.z, b.w);
        mma_tf32(acc[1][1], a[1], b.z, b.w);
    }
}
__device__ __forceinline__ void store_warp32(float* __restrict__ dst,
                                             int nw, int lane, const float acc[2][2][4]) {
    const int g = lane >> 2, tig = lane & 3;
    const int colb = nw*16 + 2*tig;
    #pragma unroll
    for (int mt = 0; mt < 2; mt++) {
        const int row = mt*16 + g;
        #pragma unroll
        for (int nn = 0; nn < 2; nn++) {
            *(float2*)(dst + row*PITCH + colb + nn*8)     = make_float2(acc[mt][nn][0], acc[mt][nn][1]);
            *(float2*)(dst + (row+8)*PITCH + colb + nn*8) = make_float2(acc[mt][nn][2], acc[mt][nn][3]);
        }
    }
}

__device__ __forceinline__ void stage_tf32(const float* __restrict__ src, float* __restrict__ dst,
                                           int tid) {
    const float4* s4 = (const float4*)src;
    for (int i = tid; i < MROWS*32; i += 256) {
        float4 x = s4[i];
        int row = i >> 5, c4 = i & 31;
        uint4 t;
        t.x = to_tf32(x.x); t.y = to_tf32(x.y); t.z = to_tf32(x.z); t.w = to_tf32(x.w);
        ((uint4*)((u32t*)dst + row*PITCH))[c4] = t;
    }
}

// ---------------------------------------------------------------------------
// Kernel 2: FUSED projections + attention middle. 2 (b,n) tiles per block,
// 3 blocks/SM, three GEMMs in one region, quad-packed weight loads.
// ---------------------------------------------------------------------------
__global__ __launch_bounds__(256, 3) void fused_kernel(const float* __restrict__ inQ,
                                                       const float* __restrict__ inK,
                                                       const float* __restrict__ inV,
                                                       const float* __restrict__ w1,
                                                       const float* __restrict__ w2,
                                                       float* __restrict__ attn_out) {
    extern __shared__ __align__(16) float sm[];
    float* sA   = sm;                 // Xq tf32 -> Q fp32 -> s_at2
    float* sB   = sm + BUFSZ;         // Xk tf32 -> K fp32
    float* sC   = sm + 2*BUFSZ;       // Xv tf32 -> V fp32
    float* s_at = sm + 3*BUFSZ;       // 2304
    float* s_w1 = sm + 3*BUFSZ + TT*HLL;        // 64
    float* s_w2 = s_w1 + 64;                    // 64
    float* s_at2 = sA;

    const int tid  = threadIdx.x;
    const int lane = tid & 31, warp = tid >> 5;
    const int bn0 = blockIdx.x * TT;
    const size_t gbase = (size_t)bn0 * (L_*D_);

    // ---- S0: stage all three inputs + mixing weights ----
    stage_tf32(inQ + gbase, sA, tid);
    stage_tf32(inK + gbase, sB, tid);
    stage_tf32(inV + gbase, sC, tid);
    if (tid < 64) { s_w1[tid] = w1[tid]; s_w2[tid] = w2[tid]; }
    __syncthreads();

    // ---- Q,K,V GEMMs: one barrier-free region ----
    {
        float acc[3][2][2][4];
        #pragma unroll
        for (int m = 0; m < 3; m++)
            #pragma unroll
            for (int mt = 0; mt < 2; mt++)
                #pragma unroll
                for (int nn = 0; nn < 2; nn++)
                    #pragma unroll
                    for (int q = 0; q < 4; q++) acc[m][mt][nn][q] = 0.f;

        #pragma unroll
        for (int m = 0; m < 3; m++)
            mma_warp32((const u32t*)(sm + m*BUFSZ), g_Wfrag[m], warp, lane, acc[m]);

        __syncthreads();     // all reads of A/B/C complete
        #pragma unroll
        for (int m = 0; m < 3; m++)
            store_warp32(sm + m*BUFSZ, warp, lane, acc[m]);
    }
    __syncthreads();

    // ---- scores + w1 mix + leaky relu (accumulate w1 on the fly) ----
    for (int idx = tid; idx < TT*LL; idx += 256) {
        int t = idx / LL, rem = idx - t*LL;
        const int i = rem / L_, j = rem - i*L_;
        const float* qrow = sA + (t*L_ + i)*PITCH;
        const float* krow = sB + (t*L_ + j)*PITCH;
        const float4* k2 = (const float4*)(g_K2 + rem*DK);
        float4 r0 = k2[0], r1 = k2[1], r2 = k2[2], r3 = k2[3];
        float out[H_];
        #pragma unroll
        for (int g2 = 0; g2 < H_; g2++) out[g2] = 0.f;
        #pragma unroll
        for (int h = 0; h < H_; h++) {
            const float4* q4 = (const float4*)(qrow + h*DK);
            const float4* k4 = (const float4*)(krow + h*DK);
            float4 q0 = q4[0], q1 = q4[1], q2 = q4[2], q3 = q4[3];
            float4 k0 = k4[0], k1 = k4[1], k2v = k4[2], k3 = k4[3];
            float s = 0.f;
            s += q0.x*(k0.x+r0.x) + q0.y*(k0.y+r0.y) + q0.z*(k0.z+r0.z) + q0.w*(k0.w+r0.w);
            s += q1.x*(k1.x+r1.x) + q1.y*(k1.y+r1.y) + q1.z*(k1.z+r1.z) + q1.w*(k1.w+r1.w);
            s += q2.x*(k2v.x+r2.x) + q2.y*(k2v.y+r2.y) + q2.z*(k2v.z+r2.z) + q2.w*(k2v.w+r2.w);
            s += q3.x*(k3.x+r3.x) + q3.y*(k3.y+r3.y) + q3.z*(k3.z+r3.z) + q3.w*(k3.w+r3.w);
            s *= 0.25f;
            #pragma unroll
            for (int g2 = 0; g2 < H_; g2++) out[g2] = fmaf(s, s_w1[h*H_ + g2], out[g2]);
        }
        #pragma unroll
        for (int g2 = 0; g2 < H_; g2++) {
            float s = out[g2];
            s_at[t*HLL + g2*LL + rem] = (s > 0.f) ? s : 0.2f * s;
        }
    }
    __syncthreads();

    // ---- softmax over k: TT*96 rows of 12 ----
    for (int rowid = tid; rowid < TT*H_*L_; rowid += 256) {
        float* row = s_at + rowid * L_;
        float mx = row[0];
        #pragma unroll
        for (int j = 1; j < L_; j++) mx = fmaxf(mx, row[j]);
        float sum = 0.f;
        #pragma unroll
        for (int j = 0; j < L_; j++) { float e = __expf(row[j] - mx); row[j] = e; sum += e; }
        float inv = 1.f / sum;
        #pragma unroll
        for (int j = 0; j < L_; j++) row[j] *= inv;
    }
    __syncthreads();

    // ---- w2 mix -> s_at2 (A region; Q dead) + attn_ret write ----
    for (int idx = tid; idx < TT*LL; idx += 256) {
        int t = idx / LL, rem = idx - t*LL;
        int i = rem / L_, j = rem - i*L_;
        float a[H_];
        #pragma unroll
        for (int h = 0; h < H_; h++) a[h] = s_at[t*HLL + h*LL + rem];
        #pragma unroll
        for (int g2 = 0; g2 < H_; g2++) {
            float s = 0.f;
            #pragma unroll
            for (int h = 0; h < H_; h++) s = fmaf(a[h], s_w2[h*H_ + g2], s);
            s_at2[t*HLL + g2*LL + rem] = s;
            attn_out[(size_t)i * ((size_t)BN*96) + (size_t)(bn0+t)*96 + g2*L_ + j] = s;
        }
    }
    __syncthreads();

    // ---- context + BN partials (coalesced [bn][c] layout) ----
    {
        const int c = tid & 127;
        const int t = tid >> 7;           // TT = 2 tiles, 128 channels each
        const int h = c >> 4, d = c & 15;
        float vj[L_];
        #pragma unroll
        for (int j = 0; j < L_; j++) vj[j] = sC[(t*L_ + j)*PITCH + c];
        const float* at = s_at2 + t*HLL + h*LL;
        float* ctxp = g_ctx + (size_t)(bn0 + t) * (L_*D_);
        float sum = 0.f, sq = 0.f;
        #pragma unroll
        for (int i = 0; i < L_; i++) {
            float a2 = 0.f;
            #pragma unroll
            for (int j = 0; j < L_; j++)
                a2 = fmaf(at[i*L_ + j], vj[j] + __ldg(g_V2 + (i*L_ + j)*DK + d), a2);
            ctxp[i*D_ + c] = a2;
            sum += a2;
            sq = fmaf(a2, a2, sq);
        }
        g_psum  [(size_t)(bn0 + t)*D_ + c] = sum;
        g_psumsq[(size_t)(bn0 + t)*D_ + c] = sq;
    }
}

// ---------------------------------------------------------------------------
// Kernel 3: finalize BN stats. 32 blocks, block b -> channels [4b, 4b+4).
// ---------------------------------------------------------------------------
__global__ void stats_kernel(const float* __restrict__ gamma, const float* __restrict__ beta) {
    __shared__ float red[8][256];
    const int tid = threadIdx.x;
    const int cb  = blockIdx.x * 4;
    float4 s  = make_float4(0.f, 0.f, 0.f, 0.f);
    float4 sq = make_float4(0.f, 0.f, 0.f, 0.f);
    for (int bn = tid; bn < BN; bn += 256) {
        float4 p = *(const float4*)(g_psum   + (size_t)bn*D_ + cb);
        float4 q = *(const float4*)(g_psumsq + (size_t)bn*D_ + cb);
        s.x += p.x; s.y += p.y; s.z += p.z; s.w += p.w;
        sq.x += q.x; sq.y += q.y; sq.z += q.z; sq.w += q.w;
    }
    red[0][tid] = s.x;  red[1][tid] = s.y;  red[2][tid] = s.z;  red[3][tid] = s.w;
    red[4][tid] = sq.x; red[5][tid] = sq.y; red[6][tid] = sq.z; red[7][tid] = sq.w;
    __syncthreads();
    for (int st = 128; st > 0; st >>= 1) {
        if (tid < st) {
            #pragma unroll
            for (int j = 0; j < 8; j++) red[j][tid] += red[j][tid + st];
        }
        __syncthreads();
    }
    if (tid < 4) {
        const float invN = 1.f / (float)ROWS;
        int c = cb + tid;
        float mean = red[tid][0] * invN;
        float var  = red[tid + 4][0] * invN - mean*mean;
        float sc = rsqrtf(var + 1e-5f) * gamma[c];
        g_scale[c] = sc;
        g_shift[c] = beta[c] - mean * sc;
    }
}

// ---------------------------------------------------------------------------
// Kernel 4: BN-apply + fc GEMM + ReLU + residual. M=32 tiles, m32n16 warps.
// ---------------------------------------------------------------------------
__global__ __launch_bounds__(256, 4) void out_kernel(const float* __restrict__ inV,
                                                     float* __restrict__ out) {
    __shared__ __align__(16) u32t s_x[MO*PITCH];
    __shared__ float s_scale[D_], s_shift[D_];
    const int tid = threadIdx.x;
    const size_t base = (size_t)blockIdx.x * MO * D_;

    if (tid < D_) { s_scale[tid] = g_scale[tid]; s_shift[tid] = g_shift[tid]; }
    __syncthreads();

    const float4* ctx4 = (const float4*)(g_ctx + base);
    const float4* sc4 = (const float4*)s_scale;
    const float4* sh4 = (const float4*)s_shift;
    for (int i = tid; i < MO*32; i += 256) {
        float4 x = ctx4[i];
        float4 sc = sc4[i & 31], sh = sh4[i & 31];
        int row = i >> 5, c4 = i & 31;
        uint4 t;
        t.x = to_tf32(x.x*sc.x + sh.x);
        t.y = to_tf32(x.y*sc.y + sh.y);
        t.z = to_tf32(x.z*sc.z + sh.z);
        t.w = to_tf32(x.w*sc.w + sh.w);
        ((uint4*)(s_x + row*PITCH))[c4] = t;
    }
    __syncthreads();

    const int lane = tid & 31, warp = tid >> 5;
    const int g = lane >> 2, tig = lane & 3;

    float acc[2][2][4];
    #pragma unroll
    for (int mt = 0; mt < 2; mt++)
        #pragma unroll
        for (int nn = 0; nn < 2; nn++)
            #pragma unroll
            for (int q = 0; q < 4; q++) acc[mt][nn][q] = 0.f;

    mma_warp32(s_x, g_Wfrag[3], warp, lane, acc);

    const float* vin = inV + base;
    float* dst = out + base;
    const int colb = warp*16 + 2*tig;
    #pragma unroll
    for (int mt = 0; mt < 2; mt++) {
        const int row = mt*16 + g;
        #pragma unroll
        for (int nn = 0; nn < 2; nn++) {
            int col = colb + nn*8;
            float2 v0 = *(const float2*)(vin + (size_t)row*D_ + col);
            float2 v1 = *(const float2*)(vin + (size_t)(row+8)*D_ + col);
            float2 o0, o1;
            o0.x = fmaxf(acc[mt][nn][0], 0.f) + v0.x;
            o0.y = fmaxf(acc[mt][nn][1], 0.f) + v0.y;
            o1.x = fmaxf(acc[mt][nn][2], 0.f) + v1.x;
            o1.y = fmaxf(acc[mt][nn][3], 0.f) + v1.y;
            *(float2*)(dst + (size_t)row*D_ + col)     = o0;
            *(float2*)(dst + (size_t)(row+8)*D_ + col) = o1;
        }
    }
}

// ---------------------------------------------------------------------------
extern "C" void kernel_launch(void* const* d_in, const int* in_sizes, int n_in,
                              void* d_out, int out_size) {
    const float* inQ   = (const float*)d_in[0];
    const float* inK   = (const float*)d_in[1];
    const float* inV   = (const float*)d_in[2];
    const float* wq_v  = (const float*)d_in[3];
    const float* wq_g  = (const float*)d_in[4];
    const float* wk_v  = (const float*)d_in[5];
    const float* wk_g  = (const float*)d_in[6];
    const float* wv_v  = (const float*)d_in[7];
    const float* wv_g  = (const float*)d_in[8];
    const float* fc_v  = (const float*)d_in[9];
    const float* fc_g  = (const float*)d_in[10];
    const float* rel_k = (const float*)d_in[11];
    const float* rel_v = (const float*)d_in[12];
    const float* w1    = (const float*)d_in[13];
    const float* w2    = (const float*)d_in[14];
    const float* gamma = (const float*)d_in[15];
    const float* beta  = (const float*)d_in[16];

    float* out      = (float*)d_out;
    float* attn_out = out + (size_t)ROWS * D_;

    const int fused_smem = (3*BUFSZ + TT*HLL + 128) * (int)sizeof(float);   // 60,416 B
    cudaFuncSetAttribute(fused_kernel, cudaFuncAttributeMaxDynamicSharedMemorySize, fused_smem);

    prep_kernel<<<5, 128>>>(wq_v, wq_g, wk_v, wk_g, wv_v, wv_g, fc_v, fc_g, rel_k, rel_v);
    fused_kernel<<<NBF, 256, fused_smem>>>(inQ, inK, inV, w1, w2, attn_out);
    stats_kernel<<<32, 256>>>(gamma, beta);
    out_kernel<<<NBO, 256>>>(inV, out);
}

// round 14
// speedup vs baseline: 1.0758x; 1.0449x over previous
#include <cuda_runtime.h>
#include <math.h>

#define B_      32
#define N_      325
#define L_      12
#define D_      128
#define H_      8
#define DK      16
#define BN      (B_*N_)        // 10400
#define ROWS    (BN*L_)        // 124800
#define MAXREL  11
#define LL      (L_*L_)        // 144
#define HLL     (H_*LL)        // 1152
#define PITCH   132
#define TT      2              // (b,n) tiles per fused block
#define MROWS   (TT*L_)        // 24 rows (no pad rows in smem now)
#define NBF     (BN/TT)        // 5200
#define BROWS   24             // buffer rows (real only)
#define BUFSZ   (BROWS*PITCH)  // 3168 floats
#define MO      32             // out_kernel row-tile
#define NBO     (ROWS/MO)      // 3900

typedef unsigned int u32t;
typedef unsigned long long u64t;

// ---- static device scratch ----
// Quad-packed tf32 weights: uint4[(kk*8+nw)*32 + lane] =
//   { nn0:b0, nn0:b1, nn1:b0, nn1:b1 } for warp nw's two n8-fragments at kk.
__device__ __align__(16) u32t  g_Wfrag[4][D_*D_];
__device__ __align__(16) float g_K2[LL*DK];
__device__ __align__(16) float g_V2[LL*DK];
__device__ __align__(16) float g_ctx[(size_t)ROWS*D_];
__device__ __align__(16) float g_psum[(size_t)BN*D_];    // [bn][c]
__device__ __align__(16) float g_psumsq[(size_t)BN*D_];  // [bn][c]
__device__ float g_scale[D_];
__device__ float g_shift[D_];

__device__ __forceinline__ u32t to_tf32(float x) {
    u32t t; asm("cvt.rna.tf32.f32 %0, %1;" : "=r"(t) : "f"(x)); return t;
}
__device__ __forceinline__ void mma_tf32(float c[4], const u32t a[4], u32t b0, u32t b1) {
    asm volatile("mma.sync.aligned.m16n8k8.row.col.f32.tf32.tf32.f32 "
                 "{%0,%1,%2,%3}, {%4,%5,%6,%7}, {%8,%9}, {%0,%1,%2,%3};"
                 : "+f"(c[0]), "+f"(c[1]), "+f"(c[2]), "+f"(c[3])
                 : "r"(a[0]), "r"(a[1]), "r"(a[2]), "r"(a[3]), "r"(b0), "r"(b1));
}
__device__ __forceinline__ u64t fma2(u64t a, u64t b, u64t c) {
    u64t d; asm("fma.rn.f32x2 %0, %1, %2, %3;" : "=l"(d) : "l"(a), "l"(b), "l"(c)); return d;
}
__device__ __forceinline__ u64t add2(u64t a, u64t b) {
    u64t d; asm("add.rn.f32x2 %0, %1, %2;" : "=l"(d) : "l"(a), "l"(b)); return d;
}
__device__ __forceinline__ u64t splat2(float a) {
    u64t d; asm("mov.b64 %0, {%1, %1};" : "=l"(d) : "f"(a)); return d;
}
__device__ __forceinline__ float hsum2(u64t v) {
    float lo, hi; asm("mov.b64 {%0,%1}, %2;" : "=f"(lo), "=f"(hi) : "l"(v)); return lo + hi;
}
__device__ __forceinline__ float2 unpack2(u64t v) {
    float lo, hi; asm("mov.b64 {%0,%1}, %2;" : "=f"(lo), "=f"(hi) : "l"(v)); return make_float2(lo, hi);
}

// ---------------------------------------------------------------------------
// Kernel 1: weight-norm -> quad-packed tf32 fragment layout; rel tables
// ---------------------------------------------------------------------------
__global__ void prep_kernel(const float* __restrict__ wq_v, const float* __restrict__ wq_g,
                            const float* __restrict__ wk_v, const float* __restrict__ wk_g,
                            const float* __restrict__ wv_v, const float* __restrict__ wv_g,
                            const float* __restrict__ fc_v, const float* __restrict__ fc_g,
                            const float* __restrict__ rel_k, const float* __restrict__ rel_v) {
    int blk = blockIdx.x;
    if (blk < 4) {
        const float* v; const float* g;
        switch (blk) {
            case 0: v = wq_v; g = wq_g; break;
            case 1: v = wk_v; g = wk_g; break;
            case 2: v = wv_v; g = wv_g; break;
            default: v = fc_v; g = fc_g; break;
        }
        __shared__ float s_sc[D_];
        int r = threadIdx.x;
        float s = 0.f;
        for (int d = 0; d < D_; d++) { float x = v[r*D_ + d]; s += x*x; }
        s_sc[r] = g[r] * rsqrtf(s);
        __syncthreads();
        for (int idx = threadIdx.x; idx < D_*D_; idx += 128) {
            int r2   = idx & 3;           // word within uint4
            int lane = (idx >> 2) & 31;
            int nw   = (idx >> 7) & 7;
            int kk   = idx >> 10;
            int nn = nw*2 + (r2 >> 1);
            int rr = r2 & 1;
            int k = kk*8 + (lane & 3) + 4*rr;
            int n = nn*8 + (lane >> 2);
            g_Wfrag[blk][idx] = to_tf32(v[n*D_ + k] * s_sc[n]);
        }
    } else {
        for (int t = threadIdx.x; t < LL; t += blockDim.x) {
            int q = t / L_, k = t % L_;
            int dist = max(-MAXREL, min(MAXREL, k - q));
            int row = dist + MAXREL;
            for (int d = 0; d < DK; d++) {
                g_K2[t*DK + d] = rel_k[row*DK + d];
                g_V2[t*DK + d] = rel_v[row*DK + d];
            }
        }
    }
}

// ---------------------------------------------------------------------------
// m32n16 warp-MMA over K=128 (quad-packed weight LDG.128). Rows 24..31 of the
// mt=1 tile read past the buffer into the NEXT allocated region (garbage ok,
// results discarded on store).
// ---------------------------------------------------------------------------
__device__ __forceinline__ void mma_warp32(const u32t* __restrict__ s_x,
                                           const u32t* __restrict__ Wf,
                                           int nw, int lane, float acc[2][2][4]) {
    const int g = lane >> 2, tig = lane & 3;
    const uint4* __restrict__ Wq = (const uint4*)Wf;
    #pragma unroll 4
    for (int kk = 0; kk < 16; kk++) {
        u32t a[2][4];
        #pragma unroll
        for (int mt = 0; mt < 2; mt++) {
            const u32t* base = s_x + (mt*16 + g)*PITCH + kk*8 + tig;
            a[mt][0] = base[0];
            a[mt][1] = base[8*PITCH];
            a[mt][2] = base[4];
            a[mt][3] = base[8*PITCH + 4];
        }
        uint4 b = Wq[(kk*8 + nw)*32 + lane];
        mma_tf32(acc[0][0], a[0], b.x, b.y);
        mma_tf32(acc[1][0], a[1], b.x, b.y);
        mma_tf32(acc[0][1], a[0], b.z, b.w);
        mma_tf32(acc[1][1], a[1], b.z, b.w);
    }
}
// Store only the 24 real rows (mt=1's second m8, rows 24..31, is garbage).
__device__ __forceinline__ void store_warp24(float* __restrict__ dst,
                                             int nw, int lane, const float acc[2][2][4]) {
    const int g = lane >> 2, tig = lane & 3;
    const int colb = nw*16 + 2*tig;
    #pragma unroll
    for (int nn = 0; nn < 2; nn++) {
        *(float2*)(dst + g*PITCH + colb + nn*8)      = make_float2(acc[0][nn][0], acc[0][nn][1]);
        *(float2*)(dst + (8+g)*PITCH + colb + nn*8)  = make_float2(acc[0][nn][2], acc[0][nn][3]);
        *(float2*)(dst + (16+g)*PITCH + colb + nn*8) = make_float2(acc[1][nn][0], acc[1][nn][1]);
    }
}

__device__ __forceinline__ void stage_tf32(const float* __restrict__ src, float* __restrict__ dst,
                                           int tid) {
    const float4* s4 = (const float4*)src;
    for (int i = tid; i < MROWS*32; i += 256) {
        float4 x = s4[i];
        int row = i >> 5, c4 = i & 31;
        uint4 t;
        t.x = to_tf32(x.x); t.y = to_tf32(x.y); t.z = to_tf32(x.z); t.w = to_tf32(x.w);
        ((uint4*)((u32t*)dst + row*PITCH))[c4] = t;
    }
}

// ---------------------------------------------------------------------------
// Kernel 2: FUSED projections + attention middle. 2 (b,n) tiles per block,
// 4 blocks/SM (47.7 KB smem), f32x2-vectorized scores/w1/w2 phases.
// ---------------------------------------------------------------------------
__global__ __launch_bounds__(256, 4) void fused_kernel(const float* __restrict__ inQ,
                                                       const float* __restrict__ inK,
                                                       const float* __restrict__ inV,
                                                       const float* __restrict__ w1,
                                                       const float* __restrict__ w2,
                                                       float* __restrict__ attn_out) {
    extern __shared__ __align__(16) float sm[];
    float* sA   = sm;                 // Xq tf32 -> Q fp32 -> s_at2
    float* sB   = sm + BUFSZ;         // Xk tf32 -> K fp32
    float* sC   = sm + 2*BUFSZ;       // Xv tf32 -> V fp32
    float* s_at = sm + 3*BUFSZ;       // 2304
    float* s_w1 = sm + 3*BUFSZ + TT*HLL;        // 64
    float* s_w2 = s_w1 + 64;                    // 64
    float* s_at2 = sA;

    const int tid  = threadIdx.x;
    const int lane = tid & 31, warp = tid >> 5;
    const int bn0 = blockIdx.x * TT;
    const size_t gbase = (size_t)bn0 * (L_*D_);

    // ---- S0: stage all three inputs + mixing weights ----
    stage_tf32(inQ + gbase, sA, tid);
    stage_tf32(inK + gbase, sB, tid);
    stage_tf32(inV + gbase, sC, tid);
    if (tid < 64) { s_w1[tid] = w1[tid]; s_w2[tid] = w2[tid]; }
    __syncthreads();

    // ---- Q,K,V GEMMs: sequential with store/next-MMA overlap ----
    {
        float accA[2][2][4], accB[2][2][4];
        #pragma unroll
        for (int mt = 0; mt < 2; mt++)
            #pragma unroll
            for (int nn = 0; nn < 2; nn++)
                #pragma unroll
                for (int q = 0; q < 4; q++) { accA[mt][nn][q] = 0.f; accB[mt][nn][q] = 0.f; }

        mma_warp32((const u32t*)sA, g_Wfrag[0], warp, lane, accA);
        __syncthreads();
        store_warp24(sA, warp, lane, accA);                       // write Q
        mma_warp32((const u32t*)sB, g_Wfrag[1], warp, lane, accB);
        __syncthreads();
        store_warp24(sB, warp, lane, accB);                       // write K
        #pragma unroll
        for (int mt = 0; mt < 2; mt++)
            #pragma unroll
            for (int nn = 0; nn < 2; nn++)
                #pragma unroll
                for (int q = 0; q < 4; q++) accA[mt][nn][q] = 0.f;
        mma_warp32((const u32t*)sC, g_Wfrag[2], warp, lane, accA);
        __syncthreads();
        store_warp24(sC, warp, lane, accA);                       // write V
    }
    __syncthreads();

    // ---- scores + w1 mix + leaky relu (f32x2) ----
    for (int idx = tid; idx < TT*LL; idx += 256) {
        int t = idx / LL, rem = idx - t*LL;
        const int i = rem / L_, j = rem - i*L_;
        const float* qrow = sA + (t*L_ + i)*PITCH;
        const float* krow = sB + (t*L_ + j)*PITCH;
        const ulonglong2* r4 = (const ulonglong2*)(g_K2 + rem*DK);
        ulonglong2 rr[4];
        #pragma unroll
        for (int p = 0; p < 4; p++) rr[p] = r4[p];
        u64t out2[4] = {0, 0, 0, 0};
        #pragma unroll
        for (int h = 0; h < H_; h++) {
            const ulonglong2* q4 = (const ulonglong2*)(qrow + h*DK);
            const ulonglong2* k4 = (const ulonglong2*)(krow + h*DK);
            u64t acc = 0;
            #pragma unroll
            for (int p = 0; p < 4; p++) {
                ulonglong2 qq = q4[p], kk = k4[p];
                acc = fma2(qq.x, add2(kk.x, rr[p].x), acc);
                acc = fma2(qq.y, add2(kk.y, rr[p].y), acc);
            }
            u64t s2 = splat2(hsum2(acc) * 0.25f);
            const u64t* w1p = (const u64t*)(s_w1 + h*H_);
            #pragma unroll
            for (int gp = 0; gp < 4; gp++) out2[gp] = fma2(s2, w1p[gp], out2[gp]);
        }
        #pragma unroll
        for (int gp = 0; gp < 4; gp++) {
            float2 o = unpack2(out2[gp]);
            s_at[t*HLL + (2*gp+0)*LL + rem] = (o.x > 0.f) ? o.x : 0.2f * o.x;
            s_at[t*HLL + (2*gp+1)*LL + rem] = (o.y > 0.f) ? o.y : 0.2f * o.y;
        }
    }
    __syncthreads();

    // ---- softmax over k: TT*96 rows of 12 ----
    for (int rowid = tid; rowid < TT*H_*L_; rowid += 256) {
        float* row = s_at + rowid * L_;
        float mx = row[0];
        #pragma unroll
        for (int j = 1; j < L_; j++) mx = fmaxf(mx, row[j]);
        float sum = 0.f;
        #pragma unroll
        for (int j = 0; j < L_; j++) { float e = __expf(row[j] - mx); row[j] = e; sum += e; }
        float inv = 1.f / sum;
        #pragma unroll
        for (int j = 0; j < L_; j++) row[j] *= inv;
    }
    __syncthreads();

    // ---- w2 mix (f32x2) -> s_at2 (A region; Q dead) + attn_ret write ----
    for (int idx = tid; idx < TT*LL; idx += 256) {
        int t = idx / LL, rem = idx - t*LL;
        int i = rem / L_, j = rem - i*L_;
        u64t out2[4] = {0, 0, 0, 0};
        #pragma unroll
        for (int h = 0; h < H_; h++) {
            u64t s2 = splat2(s_at[t*HLL + h*LL + rem]);
            const u64t* w2p = (const u64t*)(s_w2 + h*H_);
            #pragma unroll
            for (int gp = 0; gp < 4; gp++) out2[gp] = fma2(s2, w2p[gp], out2[gp]);
        }
        float* ao = attn_out + (size_t)i * ((size_t)BN*96) + (size_t)(bn0+t)*96 + j;
        #pragma unroll
        for (int gp = 0; gp < 4; gp++) {
            float2 o = unpack2(out2[gp]);
            s_at2[t*HLL + (2*gp+0)*LL + rem] = o.x;
            s_at2[t*HLL + (2*gp+1)*LL + rem] = o.y;
            ao[(2*gp+0)*L_] = o.x;
            ao[(2*gp+1)*L_] = o.y;
        }
    }
    __syncthreads();

    // ---- context + BN partials (coalesced [bn][c] layout) ----
    {
        const int c = tid & 127;
        const int t = tid >> 7;           // TT = 2 tiles, 128 channels each
        const int h = c >> 4, d = c & 15;
        float vj[L_];
        #pragma unroll
        for (int j = 0; j < L_; j++) vj[j] = sC[(t*L_ + j)*PITCH + c];
        const float* at = s_at2 + t*HLL + h*LL;
        float* ctxp = g_ctx + (size_t)(bn0 + t) * (L_*D_);
        float sum = 0.f, sq = 0.f;
        #pragma unroll
        for (int i = 0; i < L_; i++) {
            float a2 = 0.f;
            #pragma unroll
            for (int j = 0; j < L_; j++)
                a2 = fmaf(at[i*L_ + j], vj[j] + __ldg(g_V2 + (i*L_ + j)*DK + d), a2);
            ctxp[i*D_ + c] = a2;
            sum += a2;
            sq = fmaf(a2, a2, sq);
        }
        g_psum  [(size_t)(bn0 + t)*D_ + c] = sum;
        g_psumsq[(size_t)(bn0 + t)*D_ + c] = sq;
    }
}

// ---------------------------------------------------------------------------
// Kernel 3: finalize BN stats. 32 blocks, block b -> channels [4b, 4b+4).
// ---------------------------------------------------------------------------
__global__ void stats_kernel(const float* __restrict__ gamma, const float* __restrict__ beta) {
    __shared__ float red[8][256];
    const int tid = threadIdx.x;
    const int cb  = blockIdx.x * 4;
    float4 s  = make_float4(0.f, 0.f, 0.f, 0.f);
    float4 sq = make_float4(0.f, 0.f, 0.f, 0.f);
    for (int bn = tid; bn < BN; bn += 256) {
        float4 p = *(const float4*)(g_psum   + (size_t)bn*D_ + cb);
        float4 q = *(const float4*)(g_psumsq + (size_t)bn*D_ + cb);
        s.x += p.x; s.y += p.y; s.z += p.z; s.w += p.w;
        sq.x += q.x; sq.y += q.y; sq.z += q.z; sq.w += q.w;
    }
    red[0][tid] = s.x;  red[1][tid] = s.y;  red[2][tid] = s.z;  red[3][tid] = s.w;
    red[4][tid] = sq.x; red[5][tid] = sq.y; red[6][tid] = sq.z; red[7][tid] = sq.w;
    __syncthreads();
    for (int st = 128; st > 0; st >>= 1) {
        if (tid < st) {
            #pragma unroll
            for (int j = 0; j < 8; j++) red[j][tid] += red[j][tid + st];
        }
        __syncthreads();
    }
    if (tid < 4) {
        const float invN = 1.f / (float)ROWS;
        int c = cb + tid;
        float mean = red[tid][0] * invN;
        float var  = red[tid + 4][0] * invN - mean*mean;
        float sc = rsqrtf(var + 1e-5f) * gamma[c];
        g_scale[c] = sc;
        g_shift[c] = beta[c] - mean * sc;
    }
}

// ---------------------------------------------------------------------------
// Kernel 4: BN-apply + fc GEMM + ReLU + residual. M=32 tiles, m32n16 warps.
// ---------------------------------------------------------------------------
__global__ __launch_bounds__(256, 4) void out_kernel(const float* __restrict__ inV,
                                                     float* __restrict__ out) {
    __shared__ __align__(16) u32t s_x[MO*PITCH];
    __shared__ float s_scale[D_], s_shift[D_];
    const int tid = threadIdx.x;
    const size_t base = (size_t)blockIdx.x * MO * D_;

    if (tid < D_) { s_scale[tid] = g_scale[tid]; s_shift[tid] = g_shift[tid]; }
    __syncthreads();

    const float4* ctx4 = (const float4*)(g_ctx + base);
    const float4* sc4 = (const float4*)s_scale;
    const float4* sh4 = (const float4*)s_shift;
    for (int i = tid; i < MO*32; i += 256) {
        float4 x = ctx4[i];
        float4 sc = sc4[i & 31], sh = sh4[i & 31];
        int row = i >> 5, c4 = i & 31;
        uint4 t;
        t.x = to_tf32(x.x*sc.x + sh.x);
        t.y = to_tf32(x.y*sc.y + sh.y);
        t.z = to_tf32(x.z*sc.z + sh.z);
        t.w = to_tf32(x.w*sc.w + sh.w);
        ((uint4*)(s_x + row*PITCH))[c4] = t;
    }
    __syncthreads();

    const int lane = tid & 31, warp = tid >> 5;
    const int g = lane >> 2, tig = lane & 3;

    float acc[2][2][4];
    #pragma unroll
    for (int mt = 0; mt < 2; mt++)
        #pragma unroll
        for (int nn = 0; nn < 2; nn++)
            #pragma unroll
            for (int q = 0; q < 4; q++) acc[mt][nn][q] = 0.f;

    // full 32 rows here (MO=32, no pad) — same helper, all rows valid
    mma_warp32(s_x, g_Wfrag[3], warp, lane, acc);

    const float* vin = inV + base;
    float* dst = out + base;
    const int colb = warp*16 + 2*tig;
    #pragma unroll
    for (int mt = 0; mt < 2; mt++) {
        const int row = mt*16 + g;
        #pragma unroll
        for (int nn = 0; nn < 2; nn++) {
            int col = colb + nn*8;
            float2 v0 = *(const float2*)(vin + (size_t)row*D_ + col);
            float2 v1 = *(const float2*)(vin + (size_t)(row+8)*D_ + col);
            float2 o0, o1;
            o0.x = fmaxf(acc[mt][nn][0], 0.f) + v0.x;
            o0.y = fmaxf(acc[mt][nn][1], 0.f) + v0.y;
            o1.x = fmaxf(acc[mt][nn][2], 0.f) + v1.x;
            o1.y = fmaxf(acc[mt][nn][3], 0.f) + v1.y;
            *(float2*)(dst + (size_t)row*D_ + col)     = o0;
            *(float2*)(dst + (size_t)(row+8)*D_ + col) = o1;
        }
    }
}

// ---------------------------------------------------------------------------
extern "C" void kernel_launch(void* const* d_in, const int* in_sizes, int n_in,
                              void* d_out, int out_size) {
    const float* inQ   = (const float*)d_in[0];
    const float* inK   = (const float*)d_in[1];
    const float* inV   = (const float*)d_in[2];
    const float* wq_v  = (const float*)d_in[3];
    const float* wq_g  = (const float*)d_in[4];
    const float* wk_v  = (const float*)d_in[5];
    const float* wk_g  = (const float*)d_in[6];
    const float* wv_v  = (const float*)d_in[7];
    const float* wv_g  = (const float*)d_in[8];
    const float* fc_v  = (const float*)d_in[9];
    const float* fc_g  = (const float*)d_in[10];
    const float* rel_k = (const float*)d_in[11];
    const float* rel_v = (const float*)d_in[12];
    const float* w1    = (const float*)d_in[13];
    const float* w2    = (const float*)d_in[14];
    const float* gamma = (const float*)d_in[15];
    const float* beta  = (const float*)d_in[16];

    float* out      = (float*)d_out;
    float* attn_out = out + (size_t)ROWS * D_;

    const int fused_smem = (3*BUFSZ + TT*HLL + 128) * (int)sizeof(float);   // 47,744 B
    cudaFuncSetAttribute(fused_kernel, cudaFuncAttributeMaxDynamicSharedMemorySize, fused_smem);

    prep_kernel<<<5, 128>>>(wq_v, wq_g, wk_v, wk_g, wv_v, wv_g, fc_v, fc_g, rel_k, rel_v);
    fused_kernel<<<NBF, 256, fused_smem>>>(inQ, inK, inV, w1, w2, attn_out);
    stats_kernel<<<32, 256>>>(gamma, beta);
    out_kernel<<<NBO, 256>>>(inV, out);
}

// round 15
// speedup vs baseline: 1.2834x; 1.1929x over previous
#include <cuda_runtime.h>
#include <cuda_fp16.h>
#include <math.h>

#define B_      32
#define N_      325
#define L_      12
#define D_      128
#define H_      8
#define DK      16
#define BN      (B_*N_)        // 10400
#define ROWS    (BN*L_)        // 124800
#define MAXREL  11
#define LL      (L_*L_)        // 144
#define HLL     (H_*LL)        // 1152
#define PITCH   132            // fp32 result pitch (floats)
#define P16     68             // fp16 staging pitch (u32 words = 2 halves each)
#define TT      2              // (b,n) tiles per fused block
#define MROWS   (TT*L_)        // 24
#define NBF     (BN/TT)        // 5200
#define BROWS   24
#define BUFSZ   (BROWS*PITCH)  // 3168 floats
#define MO      32             // out_kernel row-tile
#define NBO     (ROWS/MO)      // 3900

typedef unsigned int u32t;
typedef unsigned long long u64t;

// ---- static device scratch ----
// Quad-packed fp16 weights: uint4[(kk*8+nw)*32 + lane] =
//   { nn0:b0, nn0:b1, nn1:b0, nn1:b1 }, each u32 = 2 halves (consecutive k).
__device__ __align__(16) u32t  g_Wfrag16[4][D_*D_/2];
__device__ __align__(16) float g_K2[LL*DK];
__device__ __align__(16) float g_V2[LL*DK];
__device__ __align__(16) float g_ctx[(size_t)ROWS*D_];
__device__ __align__(16) float g_psum[(size_t)BN*D_];    // [bn][c]
__device__ __align__(16) float g_psumsq[(size_t)BN*D_];  // [bn][c]
__device__ float g_scale[D_];
__device__ float g_shift[D_];

__device__ __forceinline__ void mma_f16(float c[4], const u32t a[4], u32t b0, u32t b1) {
    asm volatile("mma.sync.aligned.m16n8k16.row.col.f32.f16.f16.f32 "
                 "{%0,%1,%2,%3}, {%4,%5,%6,%7}, {%8,%9}, {%0,%1,%2,%3};"
                 : "+f"(c[0]), "+f"(c[1]), "+f"(c[2]), "+f"(c[3])
                 : "r"(a[0]), "r"(a[1]), "r"(a[2]), "r"(a[3]), "r"(b0), "r"(b1));
}
__device__ __forceinline__ u64t fma2(u64t a, u64t b, u64t c) {
    u64t d; asm("fma.rn.f32x2 %0, %1, %2, %3;" : "=l"(d) : "l"(a), "l"(b), "l"(c)); return d;
}
__device__ __forceinline__ u64t add2(u64t a, u64t b) {
    u64t d; asm("add.rn.f32x2 %0, %1, %2;" : "=l"(d) : "l"(a), "l"(b)); return d;
}
__device__ __forceinline__ u64t splat2(float a) {
    u64t d; asm("mov.b64 %0, {%1, %1};" : "=l"(d) : "f"(a)); return d;
}
__device__ __forceinline__ float hsum2(u64t v) {
    float lo, hi; asm("mov.b64 {%0,%1}, %2;" : "=f"(lo), "=f"(hi) : "l"(v)); return lo + hi;
}
__device__ __forceinline__ float2 unpack2(u64t v) {
    float lo, hi; asm("mov.b64 {%0,%1}, %2;" : "=f"(lo), "=f"(hi) : "l"(v)); return make_float2(lo, hi);
}
__device__ __forceinline__ u32t pack_h2(float a, float b) {
    __half2 h = __floats2half2_rn(a, b);
    return *(u32t*)&h;
}

// ---------------------------------------------------------------------------
// Kernel 1: weight-norm -> quad-packed fp16 fragment layout; rel tables
// ---------------------------------------------------------------------------
__global__ void prep_kernel(const float* __restrict__ wq_v, const float* __restrict__ wq_g,
                            const float* __restrict__ wk_v, const float* __restrict__ wk_g,
                            const float* __restrict__ wv_v, const float* __restrict__ wv_g,
                            const float* __restrict__ fc_v, const float* __restrict__ fc_g,
                            const float* __restrict__ rel_k, const float* __restrict__ rel_v) {
    int blk = blockIdx.x;
    if (blk < 4) {
        const float* v; const float* g;
        switch (blk) {
            case 0: v = wq_v; g = wq_g; break;
            case 1: v = wk_v; g = wk_g; break;
            case 2: v = wv_v; g = wv_g; break;
            default: v = fc_v; g = fc_g; break;
        }
        __shared__ float s_sc[D_];
        int r = threadIdx.x;
        float s = 0.f;
        for (int d = 0; d < D_; d++) { float x = v[r*D_ + d]; s += x*x; }
        s_sc[r] = g[r] * rsqrtf(s);
        __syncthreads();
        for (int idx = threadIdx.x; idx < D_*D_/2; idx += 128) {
            int r2   = idx & 3;           // word within uint4
            int lane = (idx >> 2) & 31;
            int nw   = (idx >> 7) & 7;
            int kk   = idx >> 10;         // 0..7
            int nn = r2 >> 1;
            int rr = r2 & 1;
            int n = nw*16 + nn*8 + (lane >> 2);
            int kb = kk*16 + rr*8 + 2*(lane & 3);
            float sc = s_sc[n];
            g_Wfrag16[blk][idx] = pack_h2(v[n*D_ + kb] * sc, v[n*D_ + kb + 1] * sc);
        }
    } else {
        for (int t = threadIdx.x; t < LL; t += blockDim.x) {
            int q = t / L_, k = t % L_;
            int dist = max(-MAXREL, min(MAXREL, k - q));
            int row = dist + MAXREL;
            for (int d = 0; d < DK; d++) {
                g_K2[t*DK + d] = rel_k[row*DK + d];
                g_V2[t*DK + d] = rel_v[row*DK + d];
            }
        }
    }
}

// ---------------------------------------------------------------------------
// m32n16 warp-MMA over K=128, fp16 (8 k-steps). s_x16: u32 words, pitch P16.
// Rows 24..31 of the mt=1 tile may be garbage (results discarded).
// ---------------------------------------------------------------------------
__device__ __forceinline__ void mma_warp32_f16(const u32t* __restrict__ s_x16,
                                               const u32t* __restrict__ Wf,
                                               int nw, int lane, float acc[2][2][4]) {
    const int g = lane >> 2, tig = lane & 3;
    const uint4* __restrict__ Wq = (const uint4*)Wf;
    #pragma unroll
    for (int kk = 0; kk < 8; kk++) {
        u32t a[2][4];
        #pragma unroll
        for (int mt = 0; mt < 2; mt++) {
            const u32t* base = s_x16 + (mt*16 + g)*P16 + kk*8 + tig;
            a[mt][0] = base[0];
            a[mt][1] = base[8*P16];
            a[mt][2] = base[4];
            a[mt][3] = base[8*P16 + 4];
        }
        uint4 b = Wq[(kk*8 + nw)*32 + lane];
        mma_f16(acc[0][0], a[0], b.x, b.y);
        mma_f16(acc[1][0], a[1], b.x, b.y);
        mma_f16(acc[0][1], a[0], b.z, b.w);
        mma_f16(acc[1][1], a[1], b.z, b.w);
    }
}
// Store only the 24 real rows (fp32, pitch PITCH).
__device__ __forceinline__ void store_warp24(float* __restrict__ dst,
                                             int nw, int lane, const float acc[2][2][4]) {
    const int g = lane >> 2, tig = lane & 3;
    const int colb = nw*16 + 2*tig;
    #pragma unroll
    for (int nn = 0; nn < 2; nn++) {
        *(float2*)(dst + g*PITCH + colb + nn*8)      = make_float2(acc[0][nn][0], acc[0][nn][1]);
        *(float2*)(dst + (8+g)*PITCH + colb + nn*8)  = make_float2(acc[0][nn][2], acc[0][nn][3]);
        *(float2*)(dst + (16+g)*PITCH + colb + nn*8) = make_float2(acc[1][nn][0], acc[1][nn][1]);
    }
}

// stage fp32 gmem -> fp16 smem (pitch P16 words), nrows*128 elements
__device__ __forceinline__ void stage_f16(const float* __restrict__ src, u32t* __restrict__ dst,
                                          int tid, int nrows) {
    const float4* s4 = (const float4*)src;
    for (int i = tid; i < nrows*32; i += 256) {
        float4 x = s4[i];
        int row = i >> 5, c4 = i & 31;
        uint2 t;
        t.x = pack_h2(x.x, x.y);
        t.y = pack_h2(x.z, x.w);
        ((uint2*)(dst + row*P16))[c4] = t;
    }
}

// ---------------------------------------------------------------------------
// Kernel 2: FUSED projections + attention middle. fp16 MMA, 4 blocks/SM.
// ---------------------------------------------------------------------------
__global__ __launch_bounds__(256, 4) void fused_kernel(const float* __restrict__ inQ,
                                                       const float* __restrict__ inK,
                                                       const float* __restrict__ inV,
                                                       const float* __restrict__ w1,
                                                       const float* __restrict__ w2,
                                                       float* __restrict__ attn_out) {
    extern __shared__ __align__(16) float sm[];
    float* sA   = sm;                 // fp16 Xq -> fp32 Q -> s_at2
    float* sB   = sm + BUFSZ;         // fp16 Xk -> fp32 K
    float* sC   = sm + 2*BUFSZ;       // fp16 Xv -> fp32 V
    float* s_at = sm + 3*BUFSZ;       // 2304
    float* s_w1 = sm + 3*BUFSZ + TT*HLL;        // 64
    float* s_w2 = s_w1 + 64;                    // 64
    float* s_at2 = sA;

    const int tid  = threadIdx.x;
    const int lane = tid & 31, warp = tid >> 5;
    const int bn0 = blockIdx.x * TT;
    const size_t gbase = (size_t)bn0 * (L_*D_);

    // ---- S0: stage all three inputs (fp16) + mixing weights ----
    stage_f16(inQ + gbase, (u32t*)sA, tid, MROWS);
    stage_f16(inK + gbase, (u32t*)sB, tid, MROWS);
    stage_f16(inV + gbase, (u32t*)sC, tid, MROWS);
    if (tid < 64) { s_w1[tid] = w1[tid]; s_w2[tid] = w2[tid]; }
    __syncthreads();

    // ---- Q,K,V GEMMs (fp16), sequential with store/next-MMA overlap ----
    {
        float accA[2][2][4], accB[2][2][4];
        #pragma unroll
        for (int mt = 0; mt < 2; mt++)
            #pragma unroll
            for (int nn = 0; nn < 2; nn++)
                #pragma unroll
                for (int q = 0; q < 4; q++) { accA[mt][nn][q] = 0.f; accB[mt][nn][q] = 0.f; }

        mma_warp32_f16((const u32t*)sA, g_Wfrag16[0], warp, lane, accA);
        __syncthreads();
        store_warp24(sA, warp, lane, accA);                       // write Q (fp32)
        mma_warp32_f16((const u32t*)sB, g_Wfrag16[1], warp, lane, accB);
        __syncthreads();
        store_warp24(sB, warp, lane, accB);                       // write K
        #pragma unroll
        for (int mt = 0; mt < 2; mt++)
            #pragma unroll
            for (int nn = 0; nn < 2; nn++)
                #pragma unroll
                for (int q = 0; q < 4; q++) accA[mt][nn][q] = 0.f;
        mma_warp32_f16((const u32t*)sC, g_Wfrag16[2], warp, lane, accA);
        __syncthreads();
        store_warp24(sC, warp, lane, accA);                       // write V
    }
    __syncthreads();

    // ---- scores + w1 mix + leaky relu (f32x2) ----
    for (int idx = tid; idx < TT*LL; idx += 256) {
        int t = idx / LL, rem = idx - t*LL;
        const int i = rem / L_, j = rem - i*L_;
        const float* qrow = sA + (t*L_ + i)*PITCH;
        const float* krow = sB + (t*L_ + j)*PITCH;
        const ulonglong2* r4 = (const ulonglong2*)(g_K2 + rem*DK);
        ulonglong2 rr[4];
        #pragma unroll
        for (int p = 0; p < 4; p++) rr[p] = r4[p];
        u64t out2[4] = {0, 0, 0, 0};
        #pragma unroll
        for (int h = 0; h < H_; h++) {
            const ulonglong2* q4 = (const ulonglong2*)(qrow + h*DK);
            const ulonglong2* k4 = (const ulonglong2*)(krow + h*DK);
            u64t acc = 0;
            #pragma unroll
            for (int p = 0; p < 4; p++) {
                ulonglong2 qq = q4[p], kk = k4[p];
                acc = fma2(qq.x, add2(kk.x, rr[p].x), acc);
                acc = fma2(qq.y, add2(kk.y, rr[p].y), acc);
            }
            u64t s2 = splat2(hsum2(acc) * 0.25f);
            const u64t* w1p = (const u64t*)(s_w1 + h*H_);
            #pragma unroll
            for (int gp = 0; gp < 4; gp++) out2[gp] = fma2(s2, w1p[gp], out2[gp]);
        }
        #pragma unroll
        for (int gp = 0; gp < 4; gp++) {
            float2 o = unpack2(out2[gp]);
            s_at[t*HLL + (2*gp+0)*LL + rem] = (o.x > 0.f) ? o.x : 0.2f * o.x;
            s_at[t*HLL + (2*gp+1)*LL + rem] = (o.y > 0.f) ? o.y : 0.2f * o.y;
        }
    }
    __syncthreads();

    // ---- softmax over k: TT*96 rows of 12 ----
    for (int rowid = tid; rowid < TT*H_*L_; rowid += 256) {
        float* row = s_at + rowid * L_;
        float mx = row[0];
        #pragma unroll
        for (int j = 1; j < L_; j++) mx = fmaxf(mx, row[j]);
        float sum = 0.f;
        #pragma unroll
        for (int j = 0; j < L_; j++) { float e = __expf(row[j] - mx); row[j] = e; sum += e; }
        float inv = 1.f / sum;
        #pragma unroll
        for (int j = 0; j < L_; j++) row[j] *= inv;
    }
    __syncthreads();

    // ---- w2 mix (f32x2) -> s_at2 + attn_ret write ----
    for (int idx = tid; idx < TT*LL; idx += 256) {
        int t = idx / LL, rem = idx - t*LL;
        int i = rem / L_, j = rem - i*L_;
        u64t out2[4] = {0, 0, 0, 0};
        #pragma unroll
        for (int h = 0; h < H_; h++) {
            u64t s2 = splat2(s_at[t*HLL + h*LL + rem]);
            const u64t* w2p = (const u64t*)(s_w2 + h*H_);
            #pragma unroll
            for (int gp = 0; gp < 4; gp++) out2[gp] = fma2(s2, w2p[gp], out2[gp]);
        }
        float* ao = attn_out + (size_t)i * ((size_t)BN*96) + (size_t)(bn0+t)*96 + j;
        #pragma unroll
        for (int gp = 0; gp < 4; gp++) {
            float2 o = unpack2(out2[gp]);
            s_at2[t*HLL + (2*gp+0)*LL + rem] = o.x;
            s_at2[t*HLL + (2*gp+1)*LL + rem] = o.y;
            ao[(2*gp+0)*L_] = o.x;
            ao[(2*gp+1)*L_] = o.y;
        }
    }
    __syncthreads();

    // ---- context + BN partials (coalesced [bn][c] layout) ----
    {
        const int c = tid & 127;
        const int t = tid >> 7;
        const int h = c >> 4, d = c & 15;
        float vj[L_];
        #pragma unroll
        for (int j = 0; j < L_; j++) vj[j] = sC[(t*L_ + j)*PITCH + c];
        const float* at = s_at2 + t*HLL + h*LL;
        float* ctxp = g_ctx + (size_t)(bn0 + t) * (L_*D_);
        float sum = 0.f, sq = 0.f;
        #pragma unroll
        for (int i = 0; i < L_; i++) {
            float a2 = 0.f;
            #pragma unroll
            for (int j = 0; j < L_; j++)
                a2 = fmaf(at[i*L_ + j], vj[j] + __ldg(g_V2 + (i*L_ + j)*DK + d), a2);
            ctxp[i*D_ + c] = a2;
            sum += a2;
            sq = fmaf(a2, a2, sq);
        }
        g_psum  [(size_t)(bn0 + t)*D_ + c] = sum;
        g_psumsq[(size_t)(bn0 + t)*D_ + c] = sq;
    }
}

// ---------------------------------------------------------------------------
// Kernel 3: finalize BN stats. 32 blocks, block b -> channels [4b, 4b+4).
// ---------------------------------------------------------------------------
__global__ void stats_kernel(const float* __restrict__ gamma, const float* __restrict__ beta) {
    __shared__ float red[8][256];
    const int tid = threadIdx.x;
    const int cb  = blockIdx.x * 4;
    float4 s  = make_float4(0.f, 0.f, 0.f, 0.f);
    float4 sq = make_float4(0.f, 0.f, 0.f, 0.f);
    for (int bn = tid; bn < BN; bn += 256) {
        float4 p = *(const float4*)(g_psum   + (size_t)bn*D_ + cb);
        float4 q = *(const float4*)(g_psumsq + (size_t)bn*D_ + cb);
        s.x += p.x; s.y += p.y; s.z += p.z; s.w += p.w;
        sq.x += q.x; sq.y += q.y; sq.z += q.z; sq.w += q.w;
    }
    red[0][tid] = s.x;  red[1][tid] = s.y;  red[2][tid] = s.z;  red[3][tid] = s.w;
    red[4][tid] = sq.x; red[5][tid] = sq.y; red[6][tid] = sq.z; red[7][tid] = sq.w;
    __syncthreads();
    for (int st = 128; st > 0; st >>= 1) {
        if (tid < st) {
            #pragma unroll
            for (int j = 0; j < 8; j++) red[j][tid] += red[j][tid + st];
        }
        __syncthreads();
    }
    if (tid < 4) {
        const float invN = 1.f / (float)ROWS;
        int c = cb + tid;
        float mean = red[tid][0] * invN;
        float var  = red[tid + 4][0] * invN - mean*mean;
        float sc = rsqrtf(var + 1e-5f) * gamma[c];
        g_scale[c] = sc;
        g_shift[c] = beta[c] - mean * sc;
    }
}

// ---------------------------------------------------------------------------
// Kernel 4: BN-apply + fc GEMM (fp16) + ReLU + residual. M=32 tiles.
// ---------------------------------------------------------------------------
__global__ __launch_bounds__(256, 4) void out_kernel(const float* __restrict__ inV,
                                                     float* __restrict__ out) {
    __shared__ __align__(16) u32t s_x[MO*P16];
    __shared__ float s_scale[D_], s_shift[D_];
    const int tid = threadIdx.x;
    const size_t base = (size_t)blockIdx.x * MO * D_;

    if (tid < D_) { s_scale[tid] = g_scale[tid]; s_shift[tid] = g_shift[tid]; }
    __syncthreads();

    const float4* ctx4 = (const float4*)(g_ctx + base);
    const float4* sc4 = (const float4*)s_scale;
    const float4* sh4 = (const float4*)s_shift;
    for (int i = tid; i < MO*32; i += 256) {
        float4 x = ctx4[i];
        float4 sc = sc4[i & 31], sh = sh4[i & 31];
        int row = i >> 5, c4 = i & 31;
        uint2 t;
        t.x = pack_h2(x.x*sc.x + sh.x, x.y*sc.y + sh.y);
        t.y = pack_h2(x.z*sc.z + sh.z, x.w*sc.w + sh.w);
        ((uint2*)(s_x + row*P16))[c4] = t;
    }
    __syncthreads();

    const int lane = tid & 31, warp = tid >> 5;
    const int g = lane >> 2, tig = lane & 3;

    float acc[2][2][4];
    #pragma unroll
    for (int mt = 0; mt < 2; mt++)
        #pragma unroll
        for (int nn = 0; nn < 2; nn++)
            #pragma unroll
            for (int q = 0; q < 4; q++) acc[mt][nn][q] = 0.f;

    mma_warp32_f16(s_x, g_Wfrag16[3], warp, lane, acc);   // all 32 rows valid

    const float* vin = inV + base;
    float* dst = out + base;
    const int colb = warp*16 + 2*tig;
    #pragma unroll
    for (int mt = 0; mt < 2; mt++) {
        const int row = mt*16 + g;
        #pragma unroll
        for (int nn = 0; nn < 2; nn++) {
            int col = colb + nn*8;
            float2 v0 = *(const float2*)(vin + (size_t)row*D_ + col);
            float2 v1 = *(const float2*)(vin + (size_t)(row+8)*D_ + col);
            float2 o0, o1;
            o0.x = fmaxf(acc[mt][nn][0], 0.f) + v0.x;
            o0.y = fmaxf(acc[mt][nn][1], 0.f) + v0.y;
            o1.x = fmaxf(acc[mt][nn][2], 0.f) + v1.x;
            o1.y = fmaxf(acc[mt][nn][3], 0.f) + v1.y;
            *(float2*)(dst + (size_t)row*D_ + col)     = o0;
            *(float2*)(dst + (size_t)(row+8)*D_ + col) = o1;
        }
    }
}

// ---------------------------------------------------------------------------
extern "C" void kernel_launch(void* const* d_in, const int* in_sizes, int n_in,
                              void* d_out, int out_size) {
    const float* inQ   = (const float*)d_in[0];
    const float* inK   = (const float*)d_in[1];
    const float* inV   = (const float*)d_in[2];
    const float* wq_v  = (const float*)d_in[3];
    const float* wq_g  = (const float*)d_in[4];
    const float* wk_v  = (const float*)d_in[5];
    const float* wk_g  = (const float*)d_in[6];
    const float* wv_v  = (const float*)d_in[7];
    const float* wv_g  = (const float*)d_in[8];
    const float* fc_v  = (const float*)d_in[9];
    const float* fc_g  = (const float*)d_in[10];
    const float* rel_k = (const float*)d_in[11];
    const float* rel_v = (const float*)d_in[12];
    const float* w1    = (const float*)d_in[13];
    const float* w2    = (const float*)d_in[14];
    const float* gamma = (const float*)d_in[15];
    const float* beta  = (const float*)d_in[16];

    float* out      = (float*)d_out;
    float* attn_out = out + (size_t)ROWS * D_;

    const int fused_smem = (3*BUFSZ + TT*HLL + 128) * (int)sizeof(float);   // 47,744 B
    cudaFuncSetAttribute(fused_kernel, cudaFuncAttributeMaxDynamicSharedMemorySize, fused_smem);

    prep_kernel<<<5, 128>>>(wq_v, wq_g, wk_v, wk_g, wv_v, wv_g, fc_v, fc_g, rel_k, rel_v);
    fused_kernel<<<NBF, 256, fused_smem>>>(inQ, inK, inV, w1, w2, attn_out);
    stats_kernel<<<32, 256>>>(gamma, beta);
    out_kernel<<<NBO, 256>>>(inV, out);
}

// round 17
// speedup vs baseline: 1.4651x; 1.1416x over previous
#include <cuda_runtime.h>
#include <cuda_fp16.h>
#include <math.h>

#define B_      32
#define N_      325
#define L_      12
#define D_      128
#define H_      8
#define DK      16
#define BN      (B_*N_)        // 10400
#define ROWS    (BN*L_)        // 124800
#define MAXREL  11
#define LL      (L_*L_)        // 144
#define HLL     (H_*LL)        // 1152
#define PITCH   132            // fp32 V pitch (floats)
#define P16     68             // fp16 pitch (u32 words)
#define TT      2
#define MROWS   (TT*L_)        // 24
#define NBF     (BN/TT)        // 5200
#define BUFSZ   (24*PITCH)     // 3168 floats (V buffer)
#define MO      32
#define NBO     (ROWS/MO)      // 3900

// fused smem offsets (float/u32 units)
#define OFF_Q   0               // u32[24*68] Xq fp16 -> Q fp16
#define OFF_K   1632            // u32[24*68] Xk fp16 -> K fp16
#define OFF_V   3264            // fp16 staging -> fp32 V, 3168 floats
#define OFF_RAW 6432            // 2304 floats: raw S1 scores
#define OFF_AT  8736            // 2304 floats: post-w1 / softmax
#define OFF_R   11040           // 2304 u32: R table fp16 [t][h][12][12w]
#define OFF_W1  13344
#define OFF_W2  13408
#define OFF_REL 13472           // 216 u32: rel_k fp16 [24][9]
#define SMTOT   13696           // floats

typedef unsigned int u32t;
typedef unsigned long long u64t;

// ---- static device scratch ----
__device__ __align__(16) u32t  g_Wfrag16[4][D_*D_/2];
__device__ __align__(16) u32t  g_rel16[24*9];
__device__ __align__(16) float g_V2[LL*DK];
__device__ __align__(16) float g_ctx[(size_t)ROWS*D_];
__device__ __align__(16) float g_psum[(size_t)BN*D_];
__device__ __align__(16) float g_psumsq[(size_t)BN*D_];
__device__ float g_scale[D_];
__device__ float g_shift[D_];

__device__ __forceinline__ void mma_f16(float c[4], const u32t a[4], u32t b0, u32t b1) {
    asm volatile("mma.sync.aligned.m16n8k16.row.col.f32.f16.f16.f32 "
                 "{%0,%1,%2,%3}, {%4,%5,%6,%7}, {%8,%9}, {%0,%1,%2,%3};"
                 : "+f"(c[0]), "+f"(c[1]), "+f"(c[2]), "+f"(c[3])
                 : "r"(a[0]), "r"(a[1]), "r"(a[2]), "r"(a[3]), "r"(b0), "r"(b1));
}
__device__ __forceinline__ u64t fma2(u64t a, u64t b, u64t c) {
    u64t d; asm("fma.rn.f32x2 %0, %1, %2, %3;" : "=l"(d) : "l"(a), "l"(b), "l"(c)); return d;
}
__device__ __forceinline__ u64t splat2(float a) {
    u64t d; asm("mov.b64 %0, {%1, %1};" : "=l"(d) : "f"(a)); return d;
}
__device__ __forceinline__ float2 unpack2(u64t v) {
    float lo, hi; asm("mov.b64 {%0,%1}, %2;" : "=f"(lo), "=f"(hi) : "l"(v)); return make_float2(lo, hi);
}
__device__ __forceinline__ u32t pack_h2(float a, float b) {
    __half2 h = __floats2half2_rn(a, b);
    return *(u32t*)&h;
}

// ---------------------------------------------------------------------------
// Kernel 1: weight-norm -> quad-packed fp16 fragments; rel_k fp16 table; V2
// ---------------------------------------------------------------------------
__global__ void prep_kernel(const float* __restrict__ wq_v, const float* __restrict__ wq_g,
                            const float* __restrict__ wk_v, const float* __restrict__ wk_g,
                            const float* __restrict__ wv_v, const float* __restrict__ wv_g,
                            const float* __restrict__ fc_v, const float* __restrict__ fc_g,
                            const float* __restrict__ rel_k, const float* __restrict__ rel_v) {
    int blk = blockIdx.x;
    if (blk < 4) {
        const float* v; const float* g;
        switch (blk) {
            case 0: v = wq_v; g = wq_g; break;
            case 1: v = wk_v; g = wk_g; break;
            case 2: v = wv_v; g = wv_g; break;
            default: v = fc_v; g = fc_g; break;
        }
        __shared__ float s_sc[D_];
        int r = threadIdx.x;
        float s = 0.f;
        for (int d = 0; d < D_; d++) { float x = v[r*D_ + d]; s += x*x; }
        s_sc[r] = g[r] * rsqrtf(s);
        __syncthreads();
        for (int idx = threadIdx.x; idx < D_*D_/2; idx += 128) {
            int r2   = idx & 3;
            int lane = (idx >> 2) & 31;
            int nw   = (idx >> 7) & 7;
            int kk   = idx >> 10;
            int nn = r2 >> 1;
            int rr = r2 & 1;
            int n = nw*16 + nn*8 + (lane >> 2);
            int kb = kk*16 + rr*8 + 2*(lane & 3);
            float sc = s_sc[n];
            g_Wfrag16[blk][idx] = pack_h2(v[n*D_ + kb] * sc, v[n*D_ + kb + 1] * sc);
        }
    } else {
        for (int t = threadIdx.x; t < LL; t += blockDim.x) {
            int q = t / L_, k = t % L_;
            int row = k - q + MAXREL;   // i,j in [0,12) -> always in range
            for (int d = 0; d < DK; d++) g_V2[t*DK + d] = rel_v[row*DK + d];
        }
        for (int idx = threadIdx.x; idx < 24*9; idx += blockDim.x) {
            int r = idx / 9, w = idx - r*9;
            u32t val = 0;
            if (r < 23 && w < 8) val = pack_h2(rel_k[r*DK + 2*w], rel_k[r*DK + 2*w + 1]);
            g_rel16[idx] = val;
        }
    }
}

// ---------------------------------------------------------------------------
// m32n16 warp-MMA over K=128, fp16. s_x16 pitch P16. Garbage tail rows ok.
// ---------------------------------------------------------------------------
__device__ __forceinline__ void mma_warp32_f16(const u32t* __restrict__ s_x16,
                                               const u32t* __restrict__ Wf,
                                               int nw, int lane, float acc[2][2][4]) {
    const int g = lane >> 2, tig = lane & 3;
    const uint4* __restrict__ Wq = (const uint4*)Wf;
    #pragma unroll
    for (int kk = 0; kk < 8; kk++) {
        u32t a[2][4];
        #pragma unroll
        for (int mt = 0; mt < 2; mt++) {
            const u32t* base = s_x16 + (mt*16 + g)*P16 + kk*8 + tig;
            a[mt][0] = base[0];
            a[mt][1] = base[8*P16];
            a[mt][2] = base[4];
            a[mt][3] = base[8*P16 + 4];
        }
        uint4 b = Wq[(kk*8 + nw)*32 + lane];
        mma_f16(acc[0][0], a[0], b.x, b.y);
        mma_f16(acc[1][0], a[1], b.x, b.y);
        mma_f16(acc[0][1], a[0], b.z, b.w);
        mma_f16(acc[1][1], a[1], b.z, b.w);
    }
}
// store 24 rows as fp16 words (for Q/K)
__device__ __forceinline__ void store24_f16(u32t* __restrict__ dst,
                                            int nw, int lane, const float acc[2][2][4]) {
    const int g = lane >> 2, tig = lane & 3;
    #pragma unroll
    for (int nn = 0; nn < 2; nn++) {
        const int cw = nw*8 + nn*4 + tig;
        dst[g*P16 + cw]      = pack_h2(acc[0][nn][0], acc[0][nn][1]);
        dst[(8+g)*P16 + cw]  = pack_h2(acc[0][nn][2], acc[0][nn][3]);
        dst[(16+g)*P16 + cw] = pack_h2(acc[1][nn][0], acc[1][nn][1]);
    }
}
// store 24 rows fp32 pitch PITCH (for V)
__device__ __forceinline__ void store24_f32(float* __restrict__ dst,
                                            int nw, int lane, const float acc[2][2][4]) {
    const int g = lane >> 2, tig = lane & 3;
    const int colb = nw*16 + 2*tig;
    #pragma unroll
    for (int nn = 0; nn < 2; nn++) {
        *(float2*)(dst + g*PITCH + colb + nn*8)      = make_float2(acc[0][nn][0], acc[0][nn][1]);
        *(float2*)(dst + (8+g)*PITCH + colb + nn*8)  = make_float2(acc[0][nn][2], acc[0][nn][3]);
        *(float2*)(dst + (16+g)*PITCH + colb + nn*8) = make_float2(acc[1][nn][0], acc[1][nn][1]);
    }
}

__device__ __forceinline__ void stage_f16(const float* __restrict__ src, u32t* __restrict__ dst,
                                          int tid, int nrows) {
    const float4* s4 = (const float4*)src;
    for (int i = tid; i < nrows*32; i += 256) {
        float4 x = s4[i];
        int row = i >> 5, c4 = i & 31;
        uint2 t;
        t.x = pack_h2(x.x, x.y);
        t.y = pack_h2(x.z, x.w);
        ((uint2*)(dst + row*P16))[c4] = t;
    }
}

// ---------------------------------------------------------------------------
// Kernel 2: FUSED projections + attention middle. MMA scores + rel-skew.
// ---------------------------------------------------------------------------
__global__ __launch_bounds__(256, 4) void fused_kernel(const float* __restrict__ inQ,
                                                       const float* __restrict__ inK,
                                                       const float* __restrict__ inV,
                                                       const float* __restrict__ w1,
                                                       const float* __restrict__ w2,
                                                       float* __restrict__ attn_out) {
    extern __shared__ __align__(16) float sm[];
    u32t*  sQ   = (u32t*)sm + OFF_Q;
    u32t*  sK   = (u32t*)sm + OFF_K;
    float* sV   = sm + OFF_V;
    float* s_raw = sm + OFF_RAW;
    float* s_at  = sm + OFF_AT;
    u32t*  sR    = (u32t*)sm + OFF_R;
    float* s_w1  = sm + OFF_W1;
    float* s_w2  = sm + OFF_W2;
    u32t*  sREL  = (u32t*)sm + OFF_REL;
    float* s_at2 = sm;     // aliases Q/K region (dead after scores)

    const int tid  = threadIdx.x;
    const int lane = tid & 31, warp = tid >> 5;
    const int g = lane >> 2, tig = lane & 3;
    const int bn0 = blockIdx.x * TT;
    const size_t gbase = (size_t)bn0 * (L_*D_);

    // ---- S0: stage inputs (fp16) + weights + rel table ----
    stage_f16(inQ + gbase, sQ, tid, MROWS);
    stage_f16(inK + gbase, sK, tid, MROWS);
    stage_f16(inV + gbase, (u32t*)sV, tid, MROWS);
    if (tid < 64) { s_w1[tid] = w1[tid]; s_w2[tid] = w2[tid]; }
    if (tid < 216) sREL[tid] = g_rel16[tid];          // FIXED: full 216-word load
    __syncthreads();

    // ---- Q,K,V GEMMs ----
    {
        float accA[2][2][4], accB[2][2][4];
        #pragma unroll
        for (int mt = 0; mt < 2; mt++)
            #pragma unroll
            for (int nn = 0; nn < 2; nn++)
                #pragma unroll
                for (int q = 0; q < 4; q++) { accA[mt][nn][q] = 0.f; accB[mt][nn][q] = 0.f; }

        mma_warp32_f16(sQ, g_Wfrag16[0], warp, lane, accA);
        __syncthreads();
        store24_f16(sQ, warp, lane, accA);
        mma_warp32_f16(sK, g_Wfrag16[1], warp, lane, accB);
        __syncthreads();
        store24_f16(sK, warp, lane, accB);
        #pragma unroll
        for (int mt = 0; mt < 2; mt++)
            #pragma unroll
            for (int nn = 0; nn < 2; nn++)
                #pragma unroll
                for (int q = 0; q < 4; q++) accA[mt][nn][q] = 0.f;
        mma_warp32_f16((const u32t*)sV, g_Wfrag16[2], warp, lane, accA);
        __syncthreads();
        store24_f32(sV, warp, lane, accA);
    }
    __syncthreads();

    // ---- scores via MMA: S1 = Qh Kh^T ; R = Qh rel_k^T ; warp = head ----
    {
        const int h = warp;
        #pragma unroll
        for (int t = 0; t < TT; t++) {
            const int aw = h*8 + tig;
            u32t A[4];
            A[0] = sQ[(t*12 + g)*P16 + aw];
            A[1] = sQ[(t*12 + g + 8)*P16 + aw];
            A[2] = sQ[(t*12 + g)*P16 + aw + 4];
            A[3] = sQ[(t*12 + g + 8)*P16 + aw + 4];
            float cj[2][4], cr[3][4];
            #pragma unroll
            for (int x = 0; x < 2; x++)
                #pragma unroll
                for (int q = 0; q < 4; q++) cj[x][q] = 0.f;
            #pragma unroll
            for (int x = 0; x < 3; x++)
                #pragma unroll
                for (int q = 0; q < 4; q++) cr[x][q] = 0.f;
            #pragma unroll
            for (int jt = 0; jt < 2; jt++) {
                int row = t*12 + jt*8 + g;
                mma_f16(cj[jt], A, sK[row*P16 + aw], sK[row*P16 + aw + 4]);
            }
            #pragma unroll
            for (int rt = 0; rt < 3; rt++) {
                int r = rt*8 + g;
                mma_f16(cr[rt], A, sREL[r*9 + tig], sREL[r*9 + tig + 4]);
            }
            // write raw S1 (fp32)
            float* raw = s_raw + (t*8 + h)*LL;
            *(float2*)(raw + g*12 + 2*tig) = make_float2(cj[0][0], cj[0][1]);
            if (g < 4)
                *(float2*)(raw + (g+8)*12 + 2*tig) = make_float2(cj[0][2], cj[0][3]);
            if (tig < 2) {
                *(float2*)(raw + g*12 + 8 + 2*tig) = make_float2(cj[1][0], cj[1][1]);
                if (g < 4)
                    *(float2*)(raw + (g+8)*12 + 8 + 2*tig) = make_float2(cj[1][2], cj[1][3]);
            }
            // write R (fp16) [i][12 words]
            u32t* Rr = sR + (t*8 + h)*LL;
            #pragma unroll
            for (int rt = 0; rt < 3; rt++) {
                int w = rt*4 + tig;
                Rr[g*12 + w] = pack_h2(cr[rt][0], cr[rt][1]);
                if (g < 4) Rr[(g+8)*12 + w] = pack_h2(cr[rt][2], cr[rt][3]);
            }
        }
    }
    __syncthreads();

    // ---- w1 mix + leaky relu (reads S1 + gathered R) ----
    for (int idx = tid; idx < TT*LL; idx += 256) {
        int t = idx / LL, rem = idx - t*LL;
        const int i = rem / L_, j = rem - i*L_;
        const int r = j - i + MAXREL;           // always in [0,22]
        const int rw = r >> 1, rodd = r & 1;
        const float* raw = s_raw + t*8*LL + rem;
        const u32t*  Rr  = sR + t*8*LL + i*12 + rw;
        u64t out2[4] = {0, 0, 0, 0};
        #pragma unroll
        for (int h = 0; h < H_; h++) {
            u32t rv = Rr[h*LL];
            __half2 hh = *(__half2*)&rv;
            float rf = rodd ? __high2float(hh) : __low2float(hh);
            float s = (raw[h*LL] + rf) * 0.25f;
            u64t s2 = splat2(s);
            const u64t* w1p = (const u64t*)(s_w1 + h*H_);
            #pragma unroll
            for (int gp = 0; gp < 4; gp++) out2[gp] = fma2(s2, w1p[gp], out2[gp]);
        }
        #pragma unroll
        for (int gp = 0; gp < 4; gp++) {
            float2 o = unpack2(out2[gp]);
            s_at[t*HLL + (2*gp+0)*LL + rem] = (o.x > 0.f) ? o.x : 0.2f * o.x;
            s_at[t*HLL + (2*gp+1)*LL + rem] = (o.y > 0.f) ? o.y : 0.2f * o.y;
        }
    }
    __syncthreads();

    // ---- softmax over k ----
    for (int rowid = tid; rowid < TT*H_*L_; rowid += 256) {
        float* row = s_at + rowid * L_;
        float mx = row[0];
        #pragma unroll
        for (int j = 1; j < L_; j++) mx = fmaxf(mx, row[j]);
        float sum = 0.f;
        #pragma unroll
        for (int j = 0; j < L_; j++) { float e = __expf(row[j] - mx); row[j] = e; sum += e; }
        float inv = 1.f / sum;
        #pragma unroll
        for (int j = 0; j < L_; j++) row[j] *= inv;
    }
    __syncthreads();

    // ---- w2 mix -> s_at2 (Q/K region, dead) + attn_ret write ----
    for (int idx = tid; idx < TT*LL; idx += 256) {
        int t = idx / LL, rem = idx - t*LL;
        int i = rem / L_, j = rem - i*L_;
        u64t out2[4] = {0, 0, 0, 0};
        #pragma unroll
        for (int h = 0; h < H_; h++) {
            u64t s2 = splat2(s_at[t*HLL + h*LL + rem]);
            const u64t* w2p = (const u64t*)(s_w2 + h*H_);
            #pragma unroll
            for (int gp = 0; gp < 4; gp++) out2[gp] = fma2(s2, w2p[gp], out2[gp]);
        }
        float* ao = attn_out + (size_t)i * ((size_t)BN*96) + (size_t)(bn0+t)*96 + j;
        #pragma unroll
        for (int gp = 0; gp < 4; gp++) {
            float2 o = unpack2(out2[gp]);
            s_at2[t*HLL + (2*gp+0)*LL + rem] = o.x;
            s_at2[t*HLL + (2*gp+1)*LL + rem] = o.y;
            ao[(2*gp+0)*L_] = o.x;
            ao[(2*gp+1)*L_] = o.y;
        }
    }
    __syncthreads();

    // ---- context + BN partials ----
    {
        const int c = tid & 127;
        const int t = tid >> 7;
        const int h = c >> 4, d = c & 15;
        float vj[L_];
        #pragma unroll
        for (int j = 0; j < L_; j++) vj[j] = sV[(t*L_ + j)*PITCH + c];
        const float* at = s_at2 + t*HLL + h*LL;
        float* ctxp = g_ctx + (size_t)(bn0 + t) * (L_*D_);
        float sum = 0.f, sq = 0.f;
        #pragma unroll
        for (int i = 0; i < L_; i++) {
            float a2 = 0.f;
            #pragma unroll
            for (int j = 0; j < L_; j++)
                a2 = fmaf(at[i*L_ + j], vj[j] + __ldg(g_V2 + (i*L_ + j)*DK + d), a2);
            ctxp[i*D_ + c] = a2;
            sum += a2;
            sq = fmaf(a2, a2, sq);
        }
        g_psum  [(size_t)(bn0 + t)*D_ + c] = sum;
        g_psumsq[(size_t)(bn0 + t)*D_ + c] = sq;
    }
}

// ---------------------------------------------------------------------------
// Kernel 3: finalize BN stats.
// ---------------------------------------------------------------------------
__global__ void stats_kernel(const float* __restrict__ gamma, const float* __restrict__ beta) {
    __shared__ float red[8][256];
    const int tid = threadIdx.x;
    const int cb  = blockIdx.x * 4;
    float4 s  = make_float4(0.f, 0.f, 0.f, 0.f);
    float4 sq = make_float4(0.f, 0.f, 0.f, 0.f);
    for (int bn = tid; bn < BN; bn += 256) {
        float4 p = *(const float4*)(g_psum   + (size_t)bn*D_ + cb);
        float4 q = *(const float4*)(g_psumsq + (size_t)bn*D_ + cb);
        s.x += p.x; s.y += p.y; s.z += p.z; s.w += p.w;
        sq.x += q.x; sq.y += q.y; sq.z += q.z; sq.w += q.w;
    }
    red[0][tid] = s.x;  red[1][tid] = s.y;  red[2][tid] = s.z;  red[3][tid] = s.w;
    red[4][tid] = sq.x; red[5][tid] = sq.y; red[6][tid] = sq.z; red[7][tid] = sq.w;
    __syncthreads();
    for (int st = 128; st > 0; st >>= 1) {
        if (tid < st) {
            #pragma unroll
            for (int j = 0; j < 8; j++) red[j][tid] += red[j][tid + st];
        }
        __syncthreads();
    }
    if (tid < 4) {
        const float invN = 1.f / (float)ROWS;
        int c = cb + tid;
        float mean = red[tid][0] * invN;
        float var  = red[tid + 4][0] * invN - mean*mean;
        float sc = rsqrtf(var + 1e-5f) * gamma[c];
        g_scale[c] = sc;
        g_shift[c] = beta[c] - mean * sc;
    }
}

// ---------------------------------------------------------------------------
// Kernel 4: BN-apply + fc GEMM (fp16) + ReLU + residual.
// ---------------------------------------------------------------------------
__global__ __launch_bounds__(256, 4) void out_kernel(const float* __restrict__ inV,
                                                     float* __restrict__ out) {
    __shared__ __align__(16) u32t s_x[MO*P16];
    __shared__ float s_scale[D_], s_shift[D_];
    const int tid = threadIdx.x;
    const size_t base = (size_t)blockIdx.x * MO * D_;

    if (tid < D_) { s_scale[tid] = g_scale[tid]; s_shift[tid] = g_shift[tid]; }
    __syncthreads();

    const float4* ctx4 = (const float4*)(g_ctx + base);
    const float4* sc4 = (const float4*)s_scale;
    const float4* sh4 = (const float4*)s_shift;
    for (int i = tid; i < MO*32; i += 256) {
        float4 x = ctx4[i];
        float4 sc = sc4[i & 31], sh = sh4[i & 31];
        int row = i >> 5, c4 = i & 31;
        uint2 t;
        t.x = pack_h2(x.x*sc.x + sh.x, x.y*sc.y + sh.y);
        t.y = pack_h2(x.z*sc.z + sh.z, x.w*sc.w + sh.w);
        ((uint2*)(s_x + row*P16))[c4] = t;
    }
    __syncthreads();

    const int lane = tid & 31, warp = tid >> 5;
    const int g = lane >> 2, tig = lane & 3;

    float acc[2][2][4];
    #pragma unroll
    for (int mt = 0; mt < 2; mt++)
        #pragma unroll
        for (int nn = 0; nn < 2; nn++)
            #pragma unroll
            for (int q = 0; q < 4; q++) acc[mt][nn][q] = 0.f;

    mma_warp32_f16(s_x, g_Wfrag16[3], warp, lane, acc);

    const float* vin = inV + base;
    float* dst = out + base;
    const int colb = warp*16 + 2*tig;
    #pragma unroll
    for (int mt = 0; mt < 2; mt++) {
        const int row = mt*16 + g;
        #pragma unroll
        for (int nn = 0; nn < 2; nn++) {
            int col = colb + nn*8;
            float2 v0 = *(const float2*)(vin + (size_t)row*D_ + col);
            float2 v1 = *(const float2*)(vin + (size_t)(row+8)*D_ + col);
            float2 o0, o1;
            o0.x = fmaxf(acc[mt][nn][0], 0.f) + v0.x;
            o0.y = fmaxf(acc[mt][nn][1], 0.f) + v0.y;
            o1.x = fmaxf(acc[mt][nn][2], 0.f) + v1.x;
            o1.y = fmaxf(acc[mt][nn][3], 0.f) + v1.y;
            *(float2*)(dst + (size_t)row*D_ + col)     = o0;
            *(float2*)(dst + (size_t)(row+8)*D_ + col) = o1;
        }
    }
}

// ---------------------------------------------------------------------------
extern "C" void kernel_launch(void* const* d_in, const int* in_sizes, int n_in,
                              void* d_out, int out_size) {
    const float* inQ   = (const float*)d_in[0];
    const float* inK   = (const float*)d_in[1];
    const float* inV   = (const float*)d_in[2];
    const float* wq_v  = (const float*)d_in[3];
    const float* wq_g  = (const float*)d_in[4];
    const float* wk_v  = (const float*)d_in[5];
    const float* wk_g  = (const float*)d_in[6];
    const float* wv_v  = (const float*)d_in[7];
    const float* wv_g  = (const float*)d_in[8];
    const float* fc_v  = (const float*)d_in[9];
    const float* fc_g  = (const float*)d_in[10];
    const float* rel_k = (const float*)d_in[11];
    const float* rel_v = (const float*)d_in[12];
    const float* w1    = (const float*)d_in[13];
    const float* w2    = (const float*)d_in[14];
    const float* gamma = (const float*)d_in[15];
    const float* beta  = (const float*)d_in[16];

    float* out      = (float*)d_out;
    float* attn_out = out + (size_t)ROWS * D_;

    const int fused_smem = SMTOT * (int)sizeof(float);   // 54,784 B
    cudaFuncSetAttribute(fused_kernel, cudaFuncAttributeMaxDynamicSharedMemorySize, fused_smem);

    prep_kernel<<<5, 128>>>(wq_v, wq_g, wk_v, wk_g, wv_v, wv_g, fc_v, fc_g, rel_k, rel_v);
    fused_kernel<<<NBF, 256, fused_smem>>>(inQ, inK, inV, w1, w2, attn_out);
    stats_kernel<<<32, 256>>>(gamma, beta);
    out_kernel<<<NBO, 256>>>(inV, out);
}